// round 1
// baseline (speedup 1.0000x reference)
#include <cuda_runtime.h>
#include <cstdint>
#include <math.h>

// Problem constants
#define Bq     4
#define Lq     4096
#define Hq     1024
#define NHq    16
#define Wq     64
#define SHIFTq 32
#define FFq    4096
#define HDq    64
#define Mq     (Bq * Lq)   // 16384 rows

// ---------------------------------------------------------------------------
// Scratch (device globals: allocation-free per harness rules)
// ---------------------------------------------------------------------------
__device__ float g_xs  [(size_t)Mq * Hq];        // shifted input (residual)
__device__ float g_qin [(size_t)Mq * Hq];        // LN1 output
__device__ float g_qkv [(size_t)Mq * 3 * Hq];    // packed qkv
__device__ float g_attn[(size_t)Mq * Hq];        // attention output
__device__ float g_xsum[(size_t)Mq * Hq];        // xs + proj(attn)
__device__ float g_z   [(size_t)Mq * Hq];        // LN2 output
__device__ float g_h1  [(size_t)Mq * FFq];       // gelu(z @ w1^T + b1)

// ---------------------------------------------------------------------------
// Helpers
// ---------------------------------------------------------------------------
__device__ __forceinline__ uint32_t f2tf(float f) {
    uint32_t u;
    asm("cvt.rna.tf32.f32 %0, %1;" : "=r"(u) : "f"(f));
    return u;
}

__device__ __forceinline__ void mma_tf32(float c[4], const uint32_t a[4], const uint32_t b[2]) {
    asm volatile(
        "mma.sync.aligned.m16n8k8.row.col.f32.tf32.tf32.f32 "
        "{%0,%1,%2,%3}, {%4,%5,%6,%7}, {%8,%9}, {%0,%1,%2,%3};\n"
        : "+f"(c[0]), "+f"(c[1]), "+f"(c[2]), "+f"(c[3])
        : "r"(a[0]), "r"(a[1]), "r"(a[2]), "r"(a[3]), "r"(b[0]), "r"(b[1]));
}

__device__ __forceinline__ float gelu_exact(float v) {
    return 0.5f * v * (1.0f + erff(v * 0.70710678118654752f));
}

// ---------------------------------------------------------------------------
// LayerNorm (+ optional roll read, + optional copy of rolled input)
// One block per row of H=1024. 256 threads, 4 elems/thread.
// y = LN(x[b, (l+shift)%L]) ; xs_out (if non-null) gets the rolled raw row.
// ---------------------------------------------------------------------------
__global__ void __launch_bounds__(256)
ln_kernel(const float* __restrict__ x, const float* __restrict__ g,
          const float* __restrict__ bb, float* __restrict__ xs_out,
          float* __restrict__ y, int shift)
{
    const int row = blockIdx.x;
    const int b   = row >> 12;          // /L
    const int l   = row & (Lq - 1);
    const int sl  = (l + shift) & (Lq - 1);
    const float* px = x + ((size_t)(b * Lq + sl)) * Hq;

    const int t = threadIdx.x;
    float v[4];
    float s = 0.f, sq = 0.f;
#pragma unroll
    for (int i = 0; i < 4; i++) {
        v[i] = px[t + i * 256];
        s  += v[i];
        sq += v[i] * v[i];
    }
#pragma unroll
    for (int o = 16; o > 0; o >>= 1) {
        s  += __shfl_xor_sync(0xffffffffu, s,  o);
        sq += __shfl_xor_sync(0xffffffffu, sq, o);
    }
    __shared__ float ws[8], wq[8];
    const int lane = t & 31, warp = t >> 5;
    if (lane == 0) { ws[warp] = s; wq[warp] = sq; }
    __syncthreads();
    if (t == 0) {
        float S = 0.f, Q = 0.f;
#pragma unroll
        for (int w = 0; w < 8; w++) { S += ws[w]; Q += wq[w]; }
        float mu  = S * (1.0f / Hq);
        float var = Q * (1.0f / Hq) - mu * mu;
        ws[0] = mu;
        wq[0] = rsqrtf(var + 1e-5f);
    }
    __syncthreads();
    const float mu = ws[0], rstd = wq[0];

    float* py = y + (size_t)row * Hq;
    float* pxs = xs_out ? xs_out + (size_t)row * Hq : nullptr;
#pragma unroll
    for (int i = 0; i < 4; i++) {
        int c = t + i * 256;
        float xv = v[i];
        py[c] = (xv - mu) * rstd * g[c] + bb[c];
        if (pxs) pxs[c] = xv;
    }
}

// ---------------------------------------------------------------------------
// Windowed attention: one block per (b, window, head). 256 threads.
// Q^T swizzled, K swizzled, V plain in 48KB smem; P reuses Q's buffer.
// ---------------------------------------------------------------------------
__global__ void __launch_bounds__(256)
attn_kernel(const float* __restrict__ qkv, float* __restrict__ attn)
{
    const int bw = blockIdx.x;                 // b * nW + w
    const int b  = bw >> 6;                    // nW = 64
    const int w  = bw & 63;
    const int h  = blockIdx.y;

    __shared__ float Qt[64 * 64];  // Qt[d*64 + ((i+d)&63)] = Q[i][d]; reused as P[c][r]
    __shared__ float Ks[64 * 64];  // Ks[c*64 + ((d+c)&63)] = K[c][d]
    __shared__ float Vs[64 * 64];  // Vs[c*64 + d]          = V[c][d]

    const int t = threadIdx.x;
    const int rowbase = b * Lq + w * 64;
    // load tiles (coalesced over d)
    for (int idx = t; idx < 4096; idx += 256) {
        int i = idx >> 6, d = idx & 63;
        size_t base = (size_t)(rowbase + i) * (3 * Hq) + h * 64 + d;
        Qt[d * 64 + ((i + d) & 63)] = qkv[base];
        Ks[i * 64 + ((d + i) & 63)] = qkv[base + Hq];
        Vs[i * 64 + d]              = qkv[base + 2 * Hq];
    }
    __syncthreads();

    const int r = t >> 2, tig = t & 3;

    // scores: thread covers row r, cols c = tig + 4j
    float s[16];
#pragma unroll
    for (int j = 0; j < 16; j++) s[j] = 0.f;
    for (int d = 0; d < 64; d++) {
        float qv = Qt[d * 64 + ((r + d) & 63)];
#pragma unroll
        for (int j = 0; j < 16; j++) {
            int c = tig + 4 * j;
            s[j] += qv * Ks[c * 64 + ((d + c) & 63)];
        }
    }
    // softmax over the row (row split across a quad of lanes)
    float mx = -1e30f;
#pragma unroll
    for (int j = 0; j < 16; j++) { s[j] *= 0.125f; mx = fmaxf(mx, s[j]); }
    mx = fmaxf(mx, __shfl_xor_sync(0xffffffffu, mx, 1));
    mx = fmaxf(mx, __shfl_xor_sync(0xffffffffu, mx, 2));
    float sum = 0.f;
#pragma unroll
    for (int j = 0; j < 16; j++) { s[j] = expf(s[j] - mx); sum += s[j]; }
    sum += __shfl_xor_sync(0xffffffffu, sum, 1);
    sum += __shfl_xor_sync(0xffffffffu, sum, 2);
    const float inv = 1.0f / sum;
#pragma unroll
    for (int j = 0; j < 16; j++) s[j] *= inv;

    __syncthreads();   // all Q reads done before P overwrites Qt
#pragma unroll
    for (int j = 0; j < 16; j++) Qt[(tig + 4 * j) * 64 + r] = s[j];  // P[c][r]
    __syncthreads();

    // O[r][d] = sum_c P[r][c] * V[c][d]; thread covers d = tig + 4j
    float acc[16];
#pragma unroll
    for (int j = 0; j < 16; j++) acc[j] = 0.f;
    for (int c = 0; c < 64; c++) {
        float pv = Qt[c * 64 + r];
#pragma unroll
        for (int j = 0; j < 16; j++)
            acc[j] += pv * Vs[c * 64 + tig + 4 * j];
    }
    float* po = attn + (size_t)(rowbase + r) * Hq + h * 64;
#pragma unroll
    for (int j = 0; j < 16; j++) po[tig + 4 * j] = acc[j];
}

// ---------------------------------------------------------------------------
// tf32 tensor-core GEMM:  C[M,N] = A[M,K] @ W[N,K]^T  + epilogue
//   MODE 0: +bias
//   MODE 1: +bias +res            (residual add)
//   MODE 2: gelu(+bias)
//   MODE 3: +bias +res, stored with row roll(+SHIFT)
// 128x128x32 tiles, 256 threads, warps 4x2, double-buffered smem.
// ---------------------------------------------------------------------------
constexpr int LDT = 36;                                     // 32 + 4 pad
constexpr int GEMM_SMEM_BYTES = 2 * 2 * 128 * LDT * 4;      // 73728

__device__ __forceinline__ void load_tile(uint32_t r[4][4], const float* __restrict__ P,
                                          int row0, int K, int kt, int t)
{
#pragma unroll
    for (int i = 0; i < 4; i++) {
        int idx = i * 256 + t;
        int m = idx >> 3, kq = idx & 7;
        const float4 f = *reinterpret_cast<const float4*>(
            P + (size_t)(row0 + m) * K + (size_t)kt * 32 + kq * 4);
        r[i][0] = f2tf(f.x); r[i][1] = f2tf(f.y);
        r[i][2] = f2tf(f.z); r[i][3] = f2tf(f.w);
    }
}

__device__ __forceinline__ void store_tile(const uint32_t r[4][4], uint32_t* s, int t)
{
#pragma unroll
    for (int i = 0; i < 4; i++) {
        int idx = i * 256 + t;
        int m = idx >> 3, kq = idx & 7;
        uint4 u; u.x = r[i][0]; u.y = r[i][1]; u.z = r[i][2]; u.w = r[i][3];
        *reinterpret_cast<uint4*>(&s[m * LDT + kq * 4]) = u;
    }
}

template <int MODE>
__global__ void __launch_bounds__(256)
gemm_tf32(const float* __restrict__ A, const float* __restrict__ Bw,
          const float* __restrict__ bias, const float* __restrict__ res,
          float* __restrict__ C, int M, int N, int K)
{
    extern __shared__ uint32_t smem[];
    uint32_t* Asm = smem;                  // [2][128][LDT]
    uint32_t* Bsm = smem + 2 * 128 * LDT;  // [2][128][LDT]

    const int t    = threadIdx.x;
    const int lane = t & 31, warp = t >> 5;
    const int gid  = lane >> 2, tig = lane & 3;
    const int wm   = warp & 3, wn = warp >> 2;
    const int rowA0 = blockIdx.y * 128;
    const int colB0 = blockIdx.x * 128;

    float acc[2][8][4];
#pragma unroll
    for (int mi = 0; mi < 2; mi++)
#pragma unroll
        for (int ni = 0; ni < 8; ni++)
#pragma unroll
            for (int c = 0; c < 4; c++) acc[mi][ni][c] = 0.f;

    uint32_t ra[4][4], rb[4][4];
    const int KT = K / 32;
    load_tile(ra, A,  rowA0, K, 0, t);
    load_tile(rb, Bw, colB0, K, 0, t);
    store_tile(ra, Asm, t);
    store_tile(rb, Bsm, t);

    for (int kt = 0; kt < KT; kt++) {
        __syncthreads();
        if (kt + 1 < KT) {
            load_tile(ra, A,  rowA0, K, kt + 1, t);
            load_tile(rb, Bw, colB0, K, kt + 1, t);
        }
        const uint32_t* as = Asm + (kt & 1) * 128 * LDT;
        const uint32_t* bs = Bsm + (kt & 1) * 128 * LDT;
#pragma unroll
        for (int k8 = 0; k8 < 4; k8++) {
            const int kk = k8 * 8;
            uint32_t af[2][4];
#pragma unroll
            for (int mi = 0; mi < 2; mi++) {
                int rb0 = wm * 32 + mi * 16;
                af[mi][0] = as[(rb0 + gid)     * LDT + kk + tig];
                af[mi][1] = as[(rb0 + gid + 8) * LDT + kk + tig];
                af[mi][2] = as[(rb0 + gid)     * LDT + kk + tig + 4];
                af[mi][3] = as[(rb0 + gid + 8) * LDT + kk + tig + 4];
            }
            uint32_t bf[8][2];
#pragma unroll
            for (int ni = 0; ni < 8; ni++) {
                int nb0 = wn * 64 + ni * 8;
                bf[ni][0] = bs[(nb0 + gid) * LDT + kk + tig];
                bf[ni][1] = bs[(nb0 + gid) * LDT + kk + tig + 4];
            }
#pragma unroll
            for (int mi = 0; mi < 2; mi++)
#pragma unroll
                for (int ni = 0; ni < 8; ni++)
                    mma_tf32(acc[mi][ni], af[mi], bf[ni]);
        }
        if (kt + 1 < KT) {
            store_tile(ra, Asm + ((kt + 1) & 1) * 128 * LDT, t);
            store_tile(rb, Bsm + ((kt + 1) & 1) * 128 * LDT, t);
        }
    }

    // epilogue
#pragma unroll
    for (int mi = 0; mi < 2; mi++)
#pragma unroll
        for (int ni = 0; ni < 8; ni++) {
            const int row = rowA0 + wm * 32 + mi * 16 + gid;
            const int col = colB0 + wn * 64 + ni * 8 + 2 * tig;
            const float bias0 = bias[col], bias1 = bias[col + 1];
#pragma unroll
            for (int hh = 0; hh < 2; hh++) {
                const int r2 = row + hh * 8;
                float v0 = acc[mi][ni][hh * 2 + 0] + bias0;
                float v1 = acc[mi][ni][hh * 2 + 1] + bias1;
                if (MODE == 1 || MODE == 3) {
                    v0 += res[(size_t)r2 * N + col];
                    v1 += res[(size_t)r2 * N + col + 1];
                }
                if (MODE == 2) { v0 = gelu_exact(v0); v1 = gelu_exact(v1); }
                int ro = r2;
                if (MODE == 3) {
                    const int bb = r2 >> 12;
                    const int l  = r2 & (Lq - 1);
                    ro = (bb << 12) | ((l + SHIFTq) & (Lq - 1));
                }
                *reinterpret_cast<float2*>(&C[(size_t)ro * N + col]) = make_float2(v0, v1);
            }
        }
}

// ---------------------------------------------------------------------------
// Launch
// ---------------------------------------------------------------------------
static float* sym_addr_xs()   { void* p; cudaGetSymbolAddress(&p, g_xs);   return (float*)p; }
static float* sym_addr_qin()  { void* p; cudaGetSymbolAddress(&p, g_qin);  return (float*)p; }
static float* sym_addr_qkv()  { void* p; cudaGetSymbolAddress(&p, g_qkv);  return (float*)p; }
static float* sym_addr_attn() { void* p; cudaGetSymbolAddress(&p, g_attn); return (float*)p; }
static float* sym_addr_xsum() { void* p; cudaGetSymbolAddress(&p, g_xsum); return (float*)p; }
static float* sym_addr_z()    { void* p; cudaGetSymbolAddress(&p, g_z);    return (float*)p; }
static float* sym_addr_h1()   { void* p; cudaGetSymbolAddress(&p, g_h1);   return (float*)p; }

extern "C" void kernel_launch(void* const* d_in, const int* in_sizes, int n_in,
                              void* d_out, int out_size)
{
    (void)in_sizes; (void)n_in; (void)out_size;
    const float* x     = (const float*)d_in[0];
    const float* ln1_g = (const float*)d_in[1];
    const float* ln1_b = (const float*)d_in[2];
    const float* in_w  = (const float*)d_in[3];
    const float* in_b  = (const float*)d_in[4];
    const float* ow    = (const float*)d_in[5];
    const float* ob    = (const float*)d_in[6];
    const float* ln2_g = (const float*)d_in[7];
    const float* ln2_b = (const float*)d_in[8];
    const float* w1    = (const float*)d_in[9];
    const float* b1    = (const float*)d_in[10];
    const float* w2    = (const float*)d_in[11];
    const float* b2    = (const float*)d_in[12];
    float* out = (float*)d_out;

    float* xs   = sym_addr_xs();
    float* qin  = sym_addr_qin();
    float* qkv  = sym_addr_qkv();
    float* attn = sym_addr_attn();
    float* xsum = sym_addr_xsum();
    float* z    = sym_addr_z();
    float* h1   = sym_addr_h1();

    cudaFuncSetAttribute(gemm_tf32<0>, cudaFuncAttributeMaxDynamicSharedMemorySize, GEMM_SMEM_BYTES);
    cudaFuncSetAttribute(gemm_tf32<1>, cudaFuncAttributeMaxDynamicSharedMemorySize, GEMM_SMEM_BYTES);
    cudaFuncSetAttribute(gemm_tf32<2>, cudaFuncAttributeMaxDynamicSharedMemorySize, GEMM_SMEM_BYTES);
    cudaFuncSetAttribute(gemm_tf32<3>, cudaFuncAttributeMaxDynamicSharedMemorySize, GEMM_SMEM_BYTES);

    // 1. roll(-SHIFT) + LN1  -> xs, qin
    ln_kernel<<<Mq, 256>>>(x, ln1_g, ln1_b, xs, qin, SHIFTq);

    // 2. qkv = qin @ in_w^T + in_b       [16384, 3072]
    gemm_tf32<0><<<dim3(3 * Hq / 128, Mq / 128), 256, GEMM_SMEM_BYTES>>>(
        qin, in_w, in_b, nullptr, qkv, Mq, 3 * Hq, Hq);

    // 3. windowed attention -> attn
    attn_kernel<<<dim3(Bq * (Lq / Wq), NHq), 256>>>(qkv, attn);

    // 4. xsum = xs + attn @ ow^T + ob    [16384, 1024]
    gemm_tf32<1><<<dim3(Hq / 128, Mq / 128), 256, GEMM_SMEM_BYTES>>>(
        attn, ow, ob, xs, xsum, Mq, Hq, Hq);

    // 5. LN2 -> z
    ln_kernel<<<Mq, 256>>>(xsum, ln2_g, ln2_b, nullptr, z, 0);

    // 6. h1 = gelu(z @ w1^T + b1)        [16384, 4096]
    gemm_tf32<2><<<dim3(FFq / 128, Mq / 128), 256, GEMM_SMEM_BYTES>>>(
        z, w1, b1, nullptr, h1, Mq, FFq, Hq);

    // 7. out = roll(+SHIFT)(xsum + h1 @ w2^T + b2)   [16384, 1024]
    gemm_tf32<3><<<dim3(Hq / 128, Mq / 128), 256, GEMM_SMEM_BYTES>>>(
        h1, w2, b2, xsum, out, Mq, Hq, FFq);
}

// round 3
// speedup vs baseline: 1.9104x; 1.9104x over previous
#include <cuda_runtime.h>
#include <cuda_fp16.h>
#include <cstdint>
#include <math.h>

// Problem constants
#define Bq     4
#define Lq     4096
#define Hq     1024
#define NHq    16
#define Wq     64
#define SHIFTq 32
#define FFq    4096
#define HDq    64
#define Mq     (Bq * Lq)   // 16384 rows

// ---------------------------------------------------------------------------
// Scratch (device globals: allocation-free per harness rules)
// ---------------------------------------------------------------------------
__device__ float g_xs  [(size_t)Mq * Hq];
__device__ float g_qin [(size_t)Mq * Hq];
__device__ float g_qkv [(size_t)Mq * 3 * Hq];
__device__ float g_attn[(size_t)Mq * Hq];
__device__ float g_xsum[(size_t)Mq * Hq];
__device__ float g_z   [(size_t)Mq * Hq];
__device__ float g_h1  [(size_t)Mq * FFq];

// ---------------------------------------------------------------------------
// Helpers
// ---------------------------------------------------------------------------
__device__ __forceinline__ void mma_f16(float c[4], const uint32_t a[4], const uint32_t b[2]) {
    asm volatile(
        "mma.sync.aligned.m16n8k16.row.col.f32.f16.f16.f32 "
        "{%0,%1,%2,%3}, {%4,%5,%6,%7}, {%8,%9}, {%0,%1,%2,%3};\n"
        : "+f"(c[0]), "+f"(c[1]), "+f"(c[2]), "+f"(c[3])
        : "r"(a[0]), "r"(a[1]), "r"(a[2]), "r"(a[3]), "r"(b[0]), "r"(b[1]));
}

__device__ __forceinline__ float gelu_exact(float v) {
    return 0.5f * v * (1.0f + erff(v * 0.70710678118654752f));
}

// ---------------------------------------------------------------------------
// LayerNorm (+ optional roll read, + optional copy of rolled input)
// ---------------------------------------------------------------------------
__global__ void __launch_bounds__(256)
ln_kernel(const float* __restrict__ x, const float* __restrict__ g,
          const float* __restrict__ bb, float* __restrict__ xs_out,
          float* __restrict__ y, int shift)
{
    const int row = blockIdx.x;
    const int b   = row >> 12;
    const int l   = row & (Lq - 1);
    const int sl  = (l + shift) & (Lq - 1);
    const float* px = x + ((size_t)(b * Lq + sl)) * Hq;

    const int t = threadIdx.x;
    float v[4];
    float s = 0.f, sq = 0.f;
#pragma unroll
    for (int i = 0; i < 4; i++) {
        v[i] = px[t + i * 256];
        s  += v[i];
        sq += v[i] * v[i];
    }
#pragma unroll
    for (int o = 16; o > 0; o >>= 1) {
        s  += __shfl_xor_sync(0xffffffffu, s,  o);
        sq += __shfl_xor_sync(0xffffffffu, sq, o);
    }
    __shared__ float ws[8], wq[8];
    const int lane = t & 31, warp = t >> 5;
    if (lane == 0) { ws[warp] = s; wq[warp] = sq; }
    __syncthreads();
    if (t == 0) {
        float S = 0.f, Q = 0.f;
#pragma unroll
        for (int w = 0; w < 8; w++) { S += ws[w]; Q += wq[w]; }
        float mu  = S * (1.0f / Hq);
        float var = Q * (1.0f / Hq) - mu * mu;
        ws[0] = mu;
        wq[0] = rsqrtf(var + 1e-5f);
    }
    __syncthreads();
    const float mu = ws[0], rstd = wq[0];

    float* py = y + (size_t)row * Hq;
    float* pxs = xs_out ? xs_out + (size_t)row * Hq : nullptr;
#pragma unroll
    for (int i = 0; i < 4; i++) {
        int c = t + i * 256;
        float xv = v[i];
        py[c] = (xv - mu) * rstd * g[c] + bb[c];
        if (pxs) pxs[c] = xv;
    }
}

// ---------------------------------------------------------------------------
// Windowed attention (verified in R1)
// ---------------------------------------------------------------------------
__global__ void __launch_bounds__(256)
attn_kernel(const float* __restrict__ qkv, float* __restrict__ attn)
{
    const int bw = blockIdx.x;
    const int b  = bw >> 6;
    const int w  = bw & 63;
    const int h  = blockIdx.y;

    __shared__ float Qt[64 * 64];
    __shared__ float Ks[64 * 64];
    __shared__ float Vs[64 * 64];

    const int t = threadIdx.x;
    const int rowbase = b * Lq + w * 64;
    for (int idx = t; idx < 4096; idx += 256) {
        int i = idx >> 6, d = idx & 63;
        size_t base = (size_t)(rowbase + i) * (3 * Hq) + h * 64 + d;
        Qt[d * 64 + ((i + d) & 63)] = qkv[base];
        Ks[i * 64 + ((d + i) & 63)] = qkv[base + Hq];
        Vs[i * 64 + d]              = qkv[base + 2 * Hq];
    }
    __syncthreads();

    const int r = t >> 2, tig = t & 3;

    float s[16];
#pragma unroll
    for (int j = 0; j < 16; j++) s[j] = 0.f;
    for (int d = 0; d < 64; d++) {
        float qv = Qt[d * 64 + ((r + d) & 63)];
#pragma unroll
        for (int j = 0; j < 16; j++) {
            int c = tig + 4 * j;
            s[j] += qv * Ks[c * 64 + ((d + c) & 63)];
        }
    }
    float mx = -1e30f;
#pragma unroll
    for (int j = 0; j < 16; j++) { s[j] *= 0.125f; mx = fmaxf(mx, s[j]); }
    mx = fmaxf(mx, __shfl_xor_sync(0xffffffffu, mx, 1));
    mx = fmaxf(mx, __shfl_xor_sync(0xffffffffu, mx, 2));
    float sum = 0.f;
#pragma unroll
    for (int j = 0; j < 16; j++) { s[j] = expf(s[j] - mx); sum += s[j]; }
    sum += __shfl_xor_sync(0xffffffffu, sum, 1);
    sum += __shfl_xor_sync(0xffffffffu, sum, 2);
    const float inv = 1.0f / sum;
#pragma unroll
    for (int j = 0; j < 16; j++) s[j] *= inv;

    __syncthreads();
#pragma unroll
    for (int j = 0; j < 16; j++) Qt[(tig + 4 * j) * 64 + r] = s[j];
    __syncthreads();

    float acc[16];
#pragma unroll
    for (int j = 0; j < 16; j++) acc[j] = 0.f;
    for (int c = 0; c < 64; c++) {
        float pv = Qt[c * 64 + r];
#pragma unroll
        for (int j = 0; j < 16; j++)
            acc[j] += pv * Vs[c * 64 + tig + 4 * j];
    }
    float* po = attn + (size_t)(rowbase + r) * Hq + h * 64;
#pragma unroll
    for (int j = 0; j < 16; j++) po[tig + 4 * j] = acc[j];
}

// ---------------------------------------------------------------------------
// fp16 tensor-core GEMM (mma.sync m16n8k16):  C = A[M,K] @ W[N,K]^T + epi
//   MODE 0: +bias   MODE 1: +bias+res   MODE 2: gelu(+bias)
//   MODE 3: +bias+res stored with row roll(+SHIFT)
// 128x128x32 tiles, 256 threads, warps 4x2 (32x64 warp tiles),
// register-prefetch double-buffered STATIC smem (40KB), 2 CTAs/SM.
// smem element = packed half2 (one k-pair). 16 pairs/row + pad -> LDT=20.
// ---------------------------------------------------------------------------
constexpr int LDT = 20;   // uint32 stride per 128-row tile (16 pairs + 4 pad)

__device__ __forceinline__ void load_tile_f16(uint32_t r[4][2], const float* __restrict__ P,
                                              int row0, int K, int kt, int t)
{
#pragma unroll
    for (int i = 0; i < 4; i++) {
        int idx = i * 256 + t;
        int m = idx >> 3, kq = idx & 7;                 // row, float4-chunk
        const float4 f = *reinterpret_cast<const float4*>(
            P + (size_t)(row0 + m) * K + (size_t)kt * 32 + kq * 4);
        __half2 h0 = __floats2half2_rn(f.x, f.y);
        __half2 h1 = __floats2half2_rn(f.z, f.w);
        r[i][0] = *reinterpret_cast<uint32_t*>(&h0);
        r[i][1] = *reinterpret_cast<uint32_t*>(&h1);
    }
}

__device__ __forceinline__ void store_tile_f16(const uint32_t r[4][2], uint32_t* s, int t)
{
#pragma unroll
    for (int i = 0; i < 4; i++) {
        int idx = i * 256 + t;
        int m = idx >> 3, kq = idx & 7;
        uint2 u; u.x = r[i][0]; u.y = r[i][1];
        *reinterpret_cast<uint2*>(&s[m * LDT + kq * 2]) = u;
    }
}

template <int MODE>
__global__ void __launch_bounds__(256, 2)
gemm_f16(const float* __restrict__ A, const float* __restrict__ Bw,
         const float* __restrict__ bias, const float* __restrict__ res,
         float* __restrict__ C, int M, int N, int K)
{
    __shared__ uint32_t Asm[2 * 128 * LDT];
    __shared__ uint32_t Bsm[2 * 128 * LDT];

    const int t    = threadIdx.x;
    const int lane = t & 31, warp = t >> 5;
    const int gid  = lane >> 2, tig = lane & 3;
    const int wm   = warp & 3, wn = warp >> 2;
    const int rowA0 = blockIdx.y * 128;
    const int colB0 = blockIdx.x * 128;

    float acc[2][8][4];
#pragma unroll
    for (int mi = 0; mi < 2; mi++)
#pragma unroll
        for (int ni = 0; ni < 8; ni++)
#pragma unroll
            for (int c = 0; c < 4; c++) acc[mi][ni][c] = 0.f;

    uint32_t ra[4][2], rb[4][2];
    const int KT = K / 32;
    load_tile_f16(ra, A,  rowA0, K, 0, t);
    load_tile_f16(rb, Bw, colB0, K, 0, t);
    store_tile_f16(ra, Asm, t);
    store_tile_f16(rb, Bsm, t);

    for (int kt = 0; kt < KT; kt++) {
        __syncthreads();
        if (kt + 1 < KT) {
            load_tile_f16(ra, A,  rowA0, K, kt + 1, t);
            load_tile_f16(rb, Bw, colB0, K, kt + 1, t);
        }
        const uint32_t* as = Asm + (kt & 1) * 128 * LDT;
        const uint32_t* bs = Bsm + (kt & 1) * 128 * LDT;
#pragma unroll
        for (int k16 = 0; k16 < 2; k16++) {
            const int kk = k16 * 8;                      // pair offset
            uint32_t af[2][4];
#pragma unroll
            for (int mi = 0; mi < 2; mi++) {
                int rb0 = wm * 32 + mi * 16;
                af[mi][0] = as[(rb0 + gid)     * LDT + kk + tig];
                af[mi][1] = as[(rb0 + gid + 8) * LDT + kk + tig];
                af[mi][2] = as[(rb0 + gid)     * LDT + kk + tig + 4];
                af[mi][3] = as[(rb0 + gid + 8) * LDT + kk + tig + 4];
            }
            uint32_t bf[8][2];
#pragma unroll
            for (int ni = 0; ni < 8; ni++) {
                int nb0 = wn * 64 + ni * 8;
                bf[ni][0] = bs[(nb0 + gid) * LDT + kk + tig];
                bf[ni][1] = bs[(nb0 + gid) * LDT + kk + tig + 4];
            }
#pragma unroll
            for (int mi = 0; mi < 2; mi++)
#pragma unroll
                for (int ni = 0; ni < 8; ni++)
                    mma_f16(acc[mi][ni], af[mi], bf[ni]);
        }
        if (kt + 1 < KT) {
            store_tile_f16(ra, Asm + ((kt + 1) & 1) * 128 * LDT, t);
            store_tile_f16(rb, Bsm + ((kt + 1) & 1) * 128 * LDT, t);
        }
    }

    // epilogue
#pragma unroll
    for (int mi = 0; mi < 2; mi++)
#pragma unroll
        for (int ni = 0; ni < 8; ni++) {
            const int row = rowA0 + wm * 32 + mi * 16 + gid;
            const int col = colB0 + wn * 64 + ni * 8 + 2 * tig;
            const float bias0 = bias[col], bias1 = bias[col + 1];
#pragma unroll
            for (int hh = 0; hh < 2; hh++) {
                const int r2 = row + hh * 8;
                float v0 = acc[mi][ni][hh * 2 + 0] + bias0;
                float v1 = acc[mi][ni][hh * 2 + 1] + bias1;
                if (MODE == 1 || MODE == 3) {
                    v0 += res[(size_t)r2 * N + col];
                    v1 += res[(size_t)r2 * N + col + 1];
                }
                if (MODE == 2) { v0 = gelu_exact(v0); v1 = gelu_exact(v1); }
                int ro = r2;
                if (MODE == 3) {
                    const int bb = r2 >> 12;
                    const int l  = r2 & (Lq - 1);
                    ro = (bb << 12) | ((l + SHIFTq) & (Lq - 1));
                }
                *reinterpret_cast<float2*>(&C[(size_t)ro * N + col]) = make_float2(v0, v1);
            }
        }
}

// ---------------------------------------------------------------------------
// Launch
// ---------------------------------------------------------------------------
static float* sym_addr_xs()   { void* p; cudaGetSymbolAddress(&p, g_xs);   return (float*)p; }
static float* sym_addr_qin()  { void* p; cudaGetSymbolAddress(&p, g_qin);  return (float*)p; }
static float* sym_addr_qkv()  { void* p; cudaGetSymbolAddress(&p, g_qkv);  return (float*)p; }
static float* sym_addr_attn() { void* p; cudaGetSymbolAddress(&p, g_attn); return (float*)p; }
static float* sym_addr_xsum() { void* p; cudaGetSymbolAddress(&p, g_xsum); return (float*)p; }
static float* sym_addr_z()    { void* p; cudaGetSymbolAddress(&p, g_z);    return (float*)p; }
static float* sym_addr_h1()   { void* p; cudaGetSymbolAddress(&p, g_h1);   return (float*)p; }

extern "C" void kernel_launch(void* const* d_in, const int* in_sizes, int n_in,
                              void* d_out, int out_size)
{
    (void)in_sizes; (void)n_in; (void)out_size;
    const float* x     = (const float*)d_in[0];
    const float* ln1_g = (const float*)d_in[1];
    const float* ln1_b = (const float*)d_in[2];
    const float* in_w  = (const float*)d_in[3];
    const float* in_b  = (const float*)d_in[4];
    const float* ow    = (const float*)d_in[5];
    const float* ob    = (const float*)d_in[6];
    const float* ln2_g = (const float*)d_in[7];
    const float* ln2_b = (const float*)d_in[8];
    const float* w1    = (const float*)d_in[9];
    const float* b1    = (const float*)d_in[10];
    const float* w2    = (const float*)d_in[11];
    const float* b2    = (const float*)d_in[12];
    float* out = (float*)d_out;

    float* xs   = sym_addr_xs();
    float* qin  = sym_addr_qin();
    float* qkv  = sym_addr_qkv();
    float* attn = sym_addr_attn();
    float* xsum = sym_addr_xsum();
    float* z    = sym_addr_z();
    float* h1   = sym_addr_h1();

    // 1. roll(-SHIFT) + LN1  -> xs, qin
    ln_kernel<<<Mq, 256>>>(x, ln1_g, ln1_b, xs, qin, SHIFTq);

    // 2. qkv = qin @ in_w^T + in_b       [16384, 3072]
    gemm_f16<0><<<dim3(3 * Hq / 128, Mq / 128), 256>>>(
        qin, in_w, in_b, nullptr, qkv, Mq, 3 * Hq, Hq);

    // 3. windowed attention -> attn
    attn_kernel<<<dim3(Bq * (Lq / Wq), NHq), 256>>>(qkv, attn);

    // 4. xsum = xs + attn @ ow^T + ob    [16384, 1024]
    gemm_f16<1><<<dim3(Hq / 128, Mq / 128), 256>>>(
        attn, ow, ob, xs, xsum, Mq, Hq, Hq);

    // 5. LN2 -> z
    ln_kernel<<<Mq, 256>>>(xsum, ln2_g, ln2_b, nullptr, z, 0);

    // 6. h1 = gelu(z @ w1^T + b1)        [16384, 4096]
    gemm_f16<2><<<dim3(FFq / 128, Mq / 128), 256>>>(
        z, w1, b1, nullptr, h1, Mq, FFq, Hq);

    // 7. out = roll(+SHIFT)(xsum + h1 @ w2^T + b2)   [16384, 1024]
    gemm_f16<3><<<dim3(Hq / 128, Mq / 128), 256>>>(
        h1, w2, b2, xsum, out, Mq, Hq, FFq);
}

// round 4
// speedup vs baseline: 2.4149x; 1.2641x over previous
#include <cuda_runtime.h>
#include <cuda_fp16.h>
#include <cstdint>
#include <math.h>

// Problem constants
#define Bq     4
#define Lq     4096
#define Hq     1024
#define NHq    16
#define Wq     64
#define SHIFTq 32
#define FFq    4096
#define HDq    64
#define Mq     (Bq * Lq)   // 16384 rows

// ---------------------------------------------------------------------------
// Scratch (device globals)
// ---------------------------------------------------------------------------
__device__ float  g_xs  [(size_t)Mq * Hq];
__device__ float  g_xsum[(size_t)Mq * Hq];
__device__ __half g_qin [(size_t)Mq * Hq];
__device__ __half g_qkv [(size_t)Mq * 3 * Hq];
__device__ __half g_attn[(size_t)Mq * Hq];
__device__ __half g_z   [(size_t)Mq * Hq];
__device__ __half g_h1  [(size_t)Mq * FFq];
__device__ __half g_wqkv[(size_t)3 * Hq * Hq];
__device__ __half g_wo  [(size_t)Hq * Hq];
__device__ __half g_w1  [(size_t)FFq * Hq];
__device__ __half g_w2  [(size_t)Hq * FFq];

// ---------------------------------------------------------------------------
// Helpers
// ---------------------------------------------------------------------------
__device__ __forceinline__ uint32_t smem_u32(const void* p) {
    uint32_t a;
    asm("{ .reg .u64 t; cvta.to.shared.u64 t, %1; cvt.u32.u64 %0, t; }" : "=r"(a) : "l"(p));
    return a;
}

__device__ __forceinline__ void mma_f16(float c[4], const uint32_t a[4], const uint32_t b[2]) {
    asm volatile(
        "mma.sync.aligned.m16n8k16.row.col.f32.f16.f16.f32 "
        "{%0,%1,%2,%3}, {%4,%5,%6,%7}, {%8,%9}, {%0,%1,%2,%3};\n"
        : "+f"(c[0]), "+f"(c[1]), "+f"(c[2]), "+f"(c[3])
        : "r"(a[0]), "r"(a[1]), "r"(a[2]), "r"(a[3]), "r"(b[0]), "r"(b[1]));
}

#define LDSM_X4(r0, r1, r2, r3, addr) \
    asm volatile("ldmatrix.sync.aligned.m8n8.x4.shared.b16 {%0,%1,%2,%3}, [%4];" \
        : "=r"(r0), "=r"(r1), "=r"(r2), "=r"(r3) : "r"(addr))

#define CP_ASYNC16(dst, src) \
    asm volatile("cp.async.cg.shared.global [%0], [%1], 16;" :: "r"(dst), "l"(src))

__device__ __forceinline__ float gelu_exact(float v) {
    return 0.5f * v * (1.0f + erff(v * 0.70710678118654752f));
}

__device__ __forceinline__ void store2(float* p, float a, float b) {
    *reinterpret_cast<float2*>(p) = make_float2(a, b);
}
__device__ __forceinline__ void store2(__half* p, float a, float b) {
    *reinterpret_cast<__half2*>(p) = __floats2half2_rn(a, b);
}

// ---------------------------------------------------------------------------
// float -> half conversion (weights, once per launch)
// ---------------------------------------------------------------------------
__global__ void __launch_bounds__(256)
f2h_kernel(const float* __restrict__ s, __half* __restrict__ d, int n)
{
    int i = (blockIdx.x * 256 + threadIdx.x) * 4;
    if (i < n) {
        float4 f = *reinterpret_cast<const float4*>(s + i);
        *reinterpret_cast<__half2*>(d + i)     = __floats2half2_rn(f.x, f.y);
        *reinterpret_cast<__half2*>(d + i + 2) = __floats2half2_rn(f.z, f.w);
    }
}

// ---------------------------------------------------------------------------
// LayerNorm (+ roll read, + optional copy of rolled raw input); output half
// ---------------------------------------------------------------------------
__global__ void __launch_bounds__(256)
ln_kernel(const float* __restrict__ x, const float* __restrict__ g,
          const float* __restrict__ bb, float* __restrict__ xs_out,
          __half* __restrict__ y, int shift)
{
    const int row = blockIdx.x;
    const int b   = row >> 12;
    const int l   = row & (Lq - 1);
    const int sl  = (l + shift) & (Lq - 1);
    const float* px = x + ((size_t)(b * Lq + sl)) * Hq;

    const int t = threadIdx.x;
    float v[4];
    float s = 0.f, sq = 0.f;
#pragma unroll
    for (int i = 0; i < 4; i++) {
        v[i] = px[t + i * 256];
        s  += v[i];
        sq += v[i] * v[i];
    }
#pragma unroll
    for (int o = 16; o > 0; o >>= 1) {
        s  += __shfl_xor_sync(0xffffffffu, s,  o);
        sq += __shfl_xor_sync(0xffffffffu, sq, o);
    }
    __shared__ float ws[8], wq[8];
    const int lane = t & 31, warp = t >> 5;
    if (lane == 0) { ws[warp] = s; wq[warp] = sq; }
    __syncthreads();
    if (t == 0) {
        float S = 0.f, Q = 0.f;
#pragma unroll
        for (int w = 0; w < 8; w++) { S += ws[w]; Q += wq[w]; }
        float mu  = S * (1.0f / Hq);
        float var = Q * (1.0f / Hq) - mu * mu;
        ws[0] = mu;
        wq[0] = rsqrtf(var + 1e-5f);
    }
    __syncthreads();
    const float mu = ws[0], rstd = wq[0];

    __half* py = y + (size_t)row * Hq;
    float* pxs = xs_out ? xs_out + (size_t)row * Hq : nullptr;
#pragma unroll
    for (int i = 0; i < 4; i++) {
        int c = t + i * 256;
        float xv = v[i];
        py[c] = __float2half((xv - mu) * rstd * g[c] + bb[c]);
        if (pxs) pxs[c] = xv;
    }
}

// ---------------------------------------------------------------------------
// Windowed attention (fp16 in/out, fp32 compute)
// ---------------------------------------------------------------------------
__global__ void __launch_bounds__(256)
attn_kernel(const __half* __restrict__ qkv, __half* __restrict__ attn)
{
    const int bw = blockIdx.x;
    const int b  = bw >> 6;
    const int w  = bw & 63;
    const int h  = blockIdx.y;

    __shared__ float Qt[64 * 64];
    __shared__ float Ks[64 * 64];
    __shared__ float Vs[64 * 64];

    const int t = threadIdx.x;
    const int rowbase = b * Lq + w * 64;
    for (int idx = t; idx < 4096; idx += 256) {
        int i = idx >> 6, d = idx & 63;
        size_t base = (size_t)(rowbase + i) * (3 * Hq) + h * 64 + d;
        Qt[d * 64 + ((i + d) & 63)] = __half2float(qkv[base]);
        Ks[i * 64 + ((d + i) & 63)] = __half2float(qkv[base + Hq]);
        Vs[i * 64 + d]              = __half2float(qkv[base + 2 * Hq]);
    }
    __syncthreads();

    const int r = t >> 2, tig = t & 3;

    float s[16];
#pragma unroll
    for (int j = 0; j < 16; j++) s[j] = 0.f;
    for (int d = 0; d < 64; d++) {
        float qv = Qt[d * 64 + ((r + d) & 63)];
#pragma unroll
        for (int j = 0; j < 16; j++) {
            int c = tig + 4 * j;
            s[j] += qv * Ks[c * 64 + ((d + c) & 63)];
        }
    }
    float mx = -1e30f;
#pragma unroll
    for (int j = 0; j < 16; j++) { s[j] *= 0.125f; mx = fmaxf(mx, s[j]); }
    mx = fmaxf(mx, __shfl_xor_sync(0xffffffffu, mx, 1));
    mx = fmaxf(mx, __shfl_xor_sync(0xffffffffu, mx, 2));
    float sum = 0.f;
#pragma unroll
    for (int j = 0; j < 16; j++) { s[j] = expf(s[j] - mx); sum += s[j]; }
    sum += __shfl_xor_sync(0xffffffffu, sum, 1);
    sum += __shfl_xor_sync(0xffffffffu, sum, 2);
    const float inv = 1.0f / sum;
#pragma unroll
    for (int j = 0; j < 16; j++) s[j] *= inv;

    __syncthreads();
#pragma unroll
    for (int j = 0; j < 16; j++) Qt[(tig + 4 * j) * 64 + r] = s[j];
    __syncthreads();

    float acc[16];
#pragma unroll
    for (int j = 0; j < 16; j++) acc[j] = 0.f;
    for (int c = 0; c < 64; c++) {
        float pv = Qt[c * 64 + r];
#pragma unroll
        for (int j = 0; j < 16; j++)
            acc[j] += pv * Vs[c * 64 + tig + 4 * j];
    }
    __half* po = attn + (size_t)(rowbase + r) * Hq + h * 64;
#pragma unroll
    for (int j = 0; j < 16; j++) po[tig + 4 * j] = __float2half(acc[j]);
}

// ---------------------------------------------------------------------------
// fp16 GEMM, cp.async + ldmatrix:  C = A[M,K] @ W[N,K]^T + epi
// Tiles: CTA 128x256x64, 8 warps (2x4), warp tile 64x64.
// 3-stage cp.async ring in dynamic smem (144KB), SW128-swizzled rows (64 halves).
//   MODE 0: +bias   MODE 1: +bias+res   MODE 2: gelu(+bias)
//   MODE 3: +bias+res, stored with row roll(+SHIFT)
// ---------------------------------------------------------------------------
constexpr int BM = 128, BN = 256, BK = 64, NST = 3;
constexpr int A_BYTES = BM * BK * 2;   // 16384
constexpr int B_BYTES = BN * BK * 2;   // 32768
constexpr int STAGE   = A_BYTES + B_BYTES;
constexpr int GSMEM   = NST * STAGE;   // 147456

__device__ __forceinline__ void gemm_load_stage(const __half* __restrict__ gA,
                                                const __half* __restrict__ gB,
                                                uint32_t sA, uint32_t sB, int K, int t)
{
#pragma unroll
    for (int i = 0; i < 4; i++) {
        int idx = t + i * 256;          // 0..1023  (A: 128 rows x 8 chunks)
        int row = idx >> 3, seg = idx & 7;
        uint32_t off = (uint32_t)(row * 128 + seg * 16);
        uint32_t sw  = off ^ ((off >> 3) & 0x70);
        CP_ASYNC16(sA + sw, gA + (size_t)row * K + seg * 8);
    }
#pragma unroll
    for (int i = 0; i < 8; i++) {
        int idx = t + i * 256;          // 0..2047  (B: 256 rows x 8 chunks)
        int row = idx >> 3, seg = idx & 7;
        uint32_t off = (uint32_t)(row * 128 + seg * 16);
        uint32_t sw  = off ^ ((off >> 3) & 0x70);
        CP_ASYNC16(sB + sw, gB + (size_t)row * K + seg * 8);
    }
}

template <int MODE, typename OutT>
__global__ void __launch_bounds__(256)
gemm_f16(const __half* __restrict__ A, const __half* __restrict__ Bw,
         const float* __restrict__ bias, const float* __restrict__ res,
         OutT* __restrict__ C, int N, int K)
{
    extern __shared__ char smem[];
    const uint32_t sb = smem_u32(smem);
    const int t    = threadIdx.x;
    const int lane = t & 31, warp = t >> 5;
    const int wm   = warp & 1, wn = warp >> 1;
    const int rowA0 = blockIdx.y * BM;
    const int colB0 = blockIdx.x * BN;

    float acc[4][8][4];
#pragma unroll
    for (int mi = 0; mi < 4; mi++)
#pragma unroll
        for (int ni = 0; ni < 8; ni++)
#pragma unroll
            for (int c = 0; c < 4; c++) acc[mi][ni][c] = 0.f;

    const int KT = K / BK;
    const __half* gA = A  + (size_t)rowA0 * K;
    const __half* gB = Bw + (size_t)colB0 * K;

    // prologue: stages 0, 1
    gemm_load_stage(gA, gB, sb, sb + A_BYTES, K, t);
    asm volatile("cp.async.commit_group;" ::: "memory");
    gemm_load_stage(gA + BK, gB + BK, sb + STAGE, sb + STAGE + A_BYTES, K, t);
    asm volatile("cp.async.commit_group;" ::: "memory");

    // lane addressing for ldmatrix
    const int lrow = lane & 15;
    const int lseg = lane >> 4;
    uint32_t aBase[4], bBase[4];
#pragma unroll
    for (int i = 0; i < 4; i++) {
        aBase[i] = (uint32_t)((wm * 64 + i * 16 + lrow) * 128 + lseg * 16);
        bBase[i] = (uint32_t)((wn * 64 + i * 16 + lrow) * 128 + lseg * 16);
    }

    for (int kt = 0; kt < KT; kt++) {
        asm volatile("cp.async.wait_group 1;" ::: "memory");
        __syncthreads();

        const int pf = kt + NST - 1;
        if (pf < KT)
            gemm_load_stage(gA + (size_t)pf * BK, gB + (size_t)pf * BK,
                            sb + (pf % NST) * STAGE, sb + (pf % NST) * STAGE + A_BYTES, K, t);
        asm volatile("cp.async.commit_group;" ::: "memory");

        const uint32_t sA = sb + (kt % NST) * STAGE;
        const uint32_t sB = sA + A_BYTES;
#pragma unroll
        for (int kk = 0; kk < 4; kk++) {
            uint32_t af[4][4], bf[8][2];
#pragma unroll
            for (int mi = 0; mi < 4; mi++) {
                uint32_t off = aBase[mi] + kk * 32;
                LDSM_X4(af[mi][0], af[mi][1], af[mi][2], af[mi][3],
                        sA + (off ^ ((off >> 3) & 0x70)));
            }
#pragma unroll
            for (int nj = 0; nj < 4; nj++) {
                uint32_t off = bBase[nj] + kk * 32;
                uint32_t r0, r1, r2, r3;
                LDSM_X4(r0, r1, r2, r3, sB + (off ^ ((off >> 3) & 0x70)));
                bf[2 * nj][0] = r0; bf[2 * nj][1] = r2;
                bf[2 * nj + 1][0] = r1; bf[2 * nj + 1][1] = r3;
            }
#pragma unroll
            for (int mi = 0; mi < 4; mi++)
#pragma unroll
                for (int ni = 0; ni < 8; ni++)
                    mma_f16(acc[mi][ni], af[mi], bf[ni]);
        }
    }

    // epilogue
    const int gid = lane >> 2, tig = lane & 3;
#pragma unroll
    for (int mi = 0; mi < 4; mi++)
#pragma unroll
        for (int ni = 0; ni < 8; ni++) {
            const int row = rowA0 + wm * 64 + mi * 16 + gid;
            const int col = colB0 + wn * 64 + ni * 8 + 2 * tig;
            const float b0 = bias[col], b1 = bias[col + 1];
#pragma unroll
            for (int hh = 0; hh < 2; hh++) {
                const int r2 = row + hh * 8;
                float v0 = acc[mi][ni][hh * 2 + 0] + b0;
                float v1 = acc[mi][ni][hh * 2 + 1] + b1;
                if (MODE == 1 || MODE == 3) {
                    v0 += res[(size_t)r2 * N + col];
                    v1 += res[(size_t)r2 * N + col + 1];
                }
                if (MODE == 2) { v0 = gelu_exact(v0); v1 = gelu_exact(v1); }
                int ro = r2;
                if (MODE == 3) {
                    const int bb = r2 >> 12;
                    const int l  = r2 & (Lq - 1);
                    ro = (bb << 12) | ((l + SHIFTq) & (Lq - 1));
                }
                store2(C + (size_t)ro * N + col, v0, v1);
            }
        }
}

// ---------------------------------------------------------------------------
// Launch
// ---------------------------------------------------------------------------
template <typename T>
static T* sym_addr(const void* sym) { void* p; cudaGetSymbolAddress(&p, sym); return (T*)p; }

extern "C" void kernel_launch(void* const* d_in, const int* in_sizes, int n_in,
                              void* d_out, int out_size)
{
    (void)in_sizes; (void)n_in; (void)out_size;
    const float* x     = (const float*)d_in[0];
    const float* ln1_g = (const float*)d_in[1];
    const float* ln1_b = (const float*)d_in[2];
    const float* in_w  = (const float*)d_in[3];
    const float* in_b  = (const float*)d_in[4];
    const float* ow    = (const float*)d_in[5];
    const float* ob    = (const float*)d_in[6];
    const float* ln2_g = (const float*)d_in[7];
    const float* ln2_b = (const float*)d_in[8];
    const float* w1    = (const float*)d_in[9];
    const float* b1    = (const float*)d_in[10];
    const float* w2    = (const float*)d_in[11];
    const float* b2    = (const float*)d_in[12];
    float* out = (float*)d_out;

    float*  xs   = sym_addr<float>(g_xs);
    float*  xsum = sym_addr<float>(g_xsum);
    __half* qin  = sym_addr<__half>(g_qin);
    __half* qkv  = sym_addr<__half>(g_qkv);
    __half* attn = sym_addr<__half>(g_attn);
    __half* z    = sym_addr<__half>(g_z);
    __half* h1   = sym_addr<__half>(g_h1);
    __half* wqkv = sym_addr<__half>(g_wqkv);
    __half* wo   = sym_addr<__half>(g_wo);
    __half* w1h  = sym_addr<__half>(g_w1);
    __half* w2h  = sym_addr<__half>(g_w2);

    cudaFuncSetAttribute(gemm_f16<0, __half>, cudaFuncAttributeMaxDynamicSharedMemorySize, GSMEM);
    cudaFuncSetAttribute(gemm_f16<1, float>,  cudaFuncAttributeMaxDynamicSharedMemorySize, GSMEM);
    cudaFuncSetAttribute(gemm_f16<2, __half>, cudaFuncAttributeMaxDynamicSharedMemorySize, GSMEM);
    cudaFuncSetAttribute(gemm_f16<3, float>,  cudaFuncAttributeMaxDynamicSharedMemorySize, GSMEM);

    // 0. convert weights to fp16
    f2h_kernel<<<(3 * Hq * Hq / 4 + 255) / 256, 256>>>(in_w, wqkv, 3 * Hq * Hq);
    f2h_kernel<<<(Hq * Hq / 4 + 255) / 256, 256>>>(ow, wo, Hq * Hq);
    f2h_kernel<<<(FFq * Hq / 4 + 255) / 256, 256>>>(w1, w1h, FFq * Hq);
    f2h_kernel<<<(Hq * FFq / 4 + 255) / 256, 256>>>(w2, w2h, Hq * FFq);

    // 1. roll(-SHIFT) + LN1 -> xs (f32), qin (f16)
    ln_kernel<<<Mq, 256>>>(x, ln1_g, ln1_b, xs, qin, SHIFTq);

    // 2. qkv = qin @ in_w^T + in_b          [16384, 3072] f16
    gemm_f16<0, __half><<<dim3(3 * Hq / BN, Mq / BM), 256, GSMEM>>>(
        qin, wqkv, in_b, nullptr, qkv, 3 * Hq, Hq);

    // 3. windowed attention -> attn (f16)
    attn_kernel<<<dim3(Bq * (Lq / Wq), NHq), 256>>>(qkv, attn);

    // 4. xsum = xs + attn @ ow^T + ob       [16384, 1024] f32
    gemm_f16<1, float><<<dim3(Hq / BN, Mq / BM), 256, GSMEM>>>(
        attn, wo, ob, xs, xsum, Hq, Hq);

    // 5. LN2 -> z (f16)
    ln_kernel<<<Mq, 256>>>(xsum, ln2_g, ln2_b, nullptr, z, 0);

    // 6. h1 = gelu(z @ w1^T + b1)           [16384, 4096] f16
    gemm_f16<2, __half><<<dim3(FFq / BN, Mq / BM), 256, GSMEM>>>(
        z, w1h, b1, nullptr, h1, FFq, Hq);

    // 7. out = roll(+SHIFT)(xsum + h1 @ w2^T + b2)   [16384, 1024] f32
    gemm_f16<3, float><<<dim3(Hq / BN, Mq / BM), 256, GSMEM>>>(
        h1, w2h, b2, xsum, out, Hq, FFq);
}

// round 6
// speedup vs baseline: 2.5686x; 1.0636x over previous
#include <cuda_runtime.h>
#include <cuda_fp16.h>
#include <cstdint>
#include <math.h>

// Problem constants
#define Bq     4
#define Lq     4096
#define Hq     1024
#define NHq    16
#define Wq     64
#define SHIFTq 32
#define FFq    4096
#define HDq    64
#define Mq     (Bq * Lq)   // 16384 rows

// ---------------------------------------------------------------------------
// Scratch (device globals)
// ---------------------------------------------------------------------------
__device__ float  g_xs  [(size_t)Mq * Hq];
__device__ float  g_xsum[(size_t)Mq * Hq];
__device__ __half g_qin [(size_t)Mq * Hq];
__device__ __half g_qkv [(size_t)Mq * 3 * Hq];
__device__ __half g_attn[(size_t)Mq * Hq];
__device__ __half g_z   [(size_t)Mq * Hq];
__device__ __half g_h1  [(size_t)Mq * FFq];
__device__ __half g_wqkv[(size_t)3 * Hq * Hq];
__device__ __half g_wo  [(size_t)Hq * Hq];
__device__ __half g_w1  [(size_t)FFq * Hq];
__device__ __half g_w2  [(size_t)Hq * FFq];

// ---------------------------------------------------------------------------
// Helpers
// ---------------------------------------------------------------------------
__device__ __forceinline__ uint32_t smem_u32(const void* p) {
    uint32_t a;
    asm("{ .reg .u64 t; cvta.to.shared.u64 t, %1; cvt.u32.u64 %0, t; }" : "=r"(a) : "l"(p));
    return a;
}

__device__ __forceinline__ void mma_f16(float c[4], const uint32_t a[4], const uint32_t b[2]) {
    asm volatile(
        "mma.sync.aligned.m16n8k16.row.col.f32.f16.f16.f32 "
        "{%0,%1,%2,%3}, {%4,%5,%6,%7}, {%8,%9}, {%0,%1,%2,%3};\n"
        : "+f"(c[0]), "+f"(c[1]), "+f"(c[2]), "+f"(c[3])
        : "r"(a[0]), "r"(a[1]), "r"(a[2]), "r"(a[3]), "r"(b[0]), "r"(b[1]));
}

#define LDSM_X4(r0, r1, r2, r3, addr) \
    asm volatile("ldmatrix.sync.aligned.m8n8.x4.shared.b16 {%0,%1,%2,%3}, [%4];" \
        : "=r"(r0), "=r"(r1), "=r"(r2), "=r"(r3) : "r"(addr))

#define CP_ASYNC16(dst, src) \
    asm volatile("cp.async.cg.shared.global [%0], [%1], 16;" :: "r"(dst), "l"(src))

__device__ __forceinline__ float gelu_exact(float v) {
    return 0.5f * v * (1.0f + erff(v * 0.70710678118654752f));
}

__device__ __forceinline__ void store2(float* p, float a, float b) {
    *reinterpret_cast<float2*>(p) = make_float2(a, b);
}
__device__ __forceinline__ void store2(__half* p, float a, float b) {
    *reinterpret_cast<__half2*>(p) = __floats2half2_rn(a, b);
}

// ---------------------------------------------------------------------------
// float -> half conversion, two arrays per launch
// ---------------------------------------------------------------------------
__global__ void __launch_bounds__(256)
f2h2_kernel(const float* __restrict__ s0, __half* __restrict__ d0, int n0,
            const float* __restrict__ s1, __half* __restrict__ d1, int n1)
{
    int i = (blockIdx.x * 256 + threadIdx.x) * 4;
    const float* s; __half* d;
    if (i < n0) { s = s0; d = d0; }
    else        { i -= n0; s = s1; d = d1; if (i >= n1) return; }
    float4 f = *reinterpret_cast<const float4*>(s + i);
    *reinterpret_cast<__half2*>(d + i)     = __floats2half2_rn(f.x, f.y);
    *reinterpret_cast<__half2*>(d + i + 2) = __floats2half2_rn(f.z, f.w);
}

// ---------------------------------------------------------------------------
// LayerNorm (+ roll read, + optional copy of rolled raw input); output half
// ---------------------------------------------------------------------------
__global__ void __launch_bounds__(256)
ln_kernel(const float* __restrict__ x, const float* __restrict__ g,
          const float* __restrict__ bb, float* __restrict__ xs_out,
          __half* __restrict__ y, int shift)
{
    const int row = blockIdx.x;
    const int b   = row >> 12;
    const int l   = row & (Lq - 1);
    const int sl  = (l + shift) & (Lq - 1);
    const float* px = x + ((size_t)(b * Lq + sl)) * Hq;

    const int t = threadIdx.x;
    float v[4];
    float s = 0.f, sq = 0.f;
#pragma unroll
    for (int i = 0; i < 4; i++) {
        v[i] = px[t + i * 256];
        s  += v[i];
        sq += v[i] * v[i];
    }
#pragma unroll
    for (int o = 16; o > 0; o >>= 1) {
        s  += __shfl_xor_sync(0xffffffffu, s,  o);
        sq += __shfl_xor_sync(0xffffffffu, sq, o);
    }
    __shared__ float ws[8], wq[8];
    const int lane = t & 31, warp = t >> 5;
    if (lane == 0) { ws[warp] = s; wq[warp] = sq; }
    __syncthreads();
    if (t == 0) {
        float S = 0.f, Q = 0.f;
#pragma unroll
        for (int w = 0; w < 8; w++) { S += ws[w]; Q += wq[w]; }
        float mu  = S * (1.0f / Hq);
        float var = Q * (1.0f / Hq) - mu * mu;
        ws[0] = mu;
        wq[0] = rsqrtf(var + 1e-5f);
    }
    __syncthreads();
    const float mu = ws[0], rstd = wq[0];

    __half* py = y + (size_t)row * Hq;
    float* pxs = xs_out ? xs_out + (size_t)row * Hq : nullptr;
#pragma unroll
    for (int i = 0; i < 4; i++) {
        int c = t + i * 256;
        float xv = v[i];
        py[c] = __float2half((xv - mu) * rstd * g[c] + bb[c]);
        if (pxs) pxs[c] = xv;
    }
}

// ---------------------------------------------------------------------------
// Windowed attention (fp16 in/out, fp32 compute)
// ---------------------------------------------------------------------------
__global__ void __launch_bounds__(256)
attn_kernel(const __half* __restrict__ qkv, __half* __restrict__ attn)
{
    const int bw = blockIdx.x;
    const int b  = bw >> 6;
    const int w  = bw & 63;
    const int h  = blockIdx.y;

    __shared__ float Qt[64 * 64];
    __shared__ float Ks[64 * 64];
    __shared__ float Vs[64 * 64];

    const int t = threadIdx.x;
    const int rowbase = b * Lq + w * 64;
    for (int idx = t; idx < 4096; idx += 256) {
        int i = idx >> 6, d = idx & 63;
        size_t base = (size_t)(rowbase + i) * (3 * Hq) + h * 64 + d;
        Qt[d * 64 + ((i + d) & 63)] = __half2float(qkv[base]);
        Ks[i * 64 + ((d + i) & 63)] = __half2float(qkv[base + Hq]);
        Vs[i * 64 + d]              = __half2float(qkv[base + 2 * Hq]);
    }
    __syncthreads();

    const int r = t >> 2, tig = t & 3;

    float s[16];
#pragma unroll
    for (int j = 0; j < 16; j++) s[j] = 0.f;
    for (int d = 0; d < 64; d++) {
        float qv = Qt[d * 64 + ((r + d) & 63)];
#pragma unroll
        for (int j = 0; j < 16; j++) {
            int c = tig + 4 * j;
            s[j] += qv * Ks[c * 64 + ((d + c) & 63)];
        }
    }
    float mx = -1e30f;
#pragma unroll
    for (int j = 0; j < 16; j++) { s[j] *= 0.125f; mx = fmaxf(mx, s[j]); }
    mx = fmaxf(mx, __shfl_xor_sync(0xffffffffu, mx, 1));
    mx = fmaxf(mx, __shfl_xor_sync(0xffffffffu, mx, 2));
    float sum = 0.f;
#pragma unroll
    for (int j = 0; j < 16; j++) { s[j] = expf(s[j] - mx); sum += s[j]; }
    sum += __shfl_xor_sync(0xffffffffu, sum, 1);
    sum += __shfl_xor_sync(0xffffffffu, sum, 2);
    const float inv = 1.0f / sum;
#pragma unroll
    for (int j = 0; j < 16; j++) s[j] *= inv;

    __syncthreads();
#pragma unroll
    for (int j = 0; j < 16; j++) Qt[(tig + 4 * j) * 64 + r] = s[j];
    __syncthreads();

    float acc[16];
#pragma unroll
    for (int j = 0; j < 16; j++) acc[j] = 0.f;
    for (int c = 0; c < 64; c++) {
        float pv = Qt[c * 64 + r];
#pragma unroll
        for (int j = 0; j < 16; j++)
            acc[j] += pv * Vs[c * 64 + tig + 4 * j];
    }
    __half* po = attn + (size_t)(rowbase + r) * Hq + h * 64;
#pragma unroll
    for (int j = 0; j < 16; j++) po[tig + 4 * j] = __float2half(acc[j]);
}

// ---------------------------------------------------------------------------
// fp16 GEMM, cp.async + ldmatrix:  C = A[M,K] @ W[N,K]^T + epi
// CTA 128x256x64, 8 warps (2x4), warp tile 64x64.
// 4-stage cp.async ring (192KB), SW128-swizzled rows.
// Mainloop: consume kk=0, then issue prefetch, then kk=1..3.
// ldmatrix addressing: base offset and row-mask precomputed; XOR applied
// AFTER the +kk*32 add (correct; R5 applied it before -> address carry bug).
//   MODE 0: +bias   MODE 1: +bias+res   MODE 2: gelu(+bias)
//   MODE 3: +bias+res, stored with row roll(+SHIFT)
// ---------------------------------------------------------------------------
constexpr int BM = 128, BN = 256, BK = 64, NST = 4;
constexpr int A_BYTES = BM * BK * 2;   // 16384
constexpr int B_BYTES = BN * BK * 2;   // 32768
constexpr int STAGE   = A_BYTES + B_BYTES;
constexpr int GSMEM   = NST * STAGE;   // 196608

__device__ __forceinline__ void gemm_load_stage(const __half* __restrict__ gA,
                                                const __half* __restrict__ gB,
                                                uint32_t sA, uint32_t sB, int K, int t)
{
#pragma unroll
    for (int i = 0; i < 4; i++) {
        int idx = t + i * 256;
        int row = idx >> 3, seg = idx & 7;
        uint32_t off = (uint32_t)(row * 128 + seg * 16);
        uint32_t sw  = off ^ ((off >> 3) & 0x70);
        CP_ASYNC16(sA + sw, gA + (size_t)row * K + seg * 8);
    }
#pragma unroll
    for (int i = 0; i < 8; i++) {
        int idx = t + i * 256;
        int row = idx >> 3, seg = idx & 7;
        uint32_t off = (uint32_t)(row * 128 + seg * 16);
        uint32_t sw  = off ^ ((off >> 3) & 0x70);
        CP_ASYNC16(sB + sw, gB + (size_t)row * K + seg * 8);
    }
}

template <int MODE, typename OutT>
__global__ void __launch_bounds__(256)
gemm_f16(const __half* __restrict__ A, const __half* __restrict__ Bw,
         const float* __restrict__ bias, const float* __restrict__ res,
         OutT* __restrict__ C, int N, int K)
{
    extern __shared__ char smem[];
    const uint32_t sb = smem_u32(smem);
    const int t    = threadIdx.x;
    const int lane = t & 31, warp = t >> 5;
    const int wm   = warp & 1, wn = warp >> 1;
    const int rowA0 = blockIdx.y * BM;
    const int colB0 = blockIdx.x * BN;

    float acc[4][8][4];
#pragma unroll
    for (int mi = 0; mi < 4; mi++)
#pragma unroll
        for (int ni = 0; ni < 8; ni++)
#pragma unroll
            for (int c = 0; c < 4; c++) acc[mi][ni][c] = 0.f;

    const int KT = K / BK;
    const __half* gA = A  + (size_t)rowA0 * K;
    const __half* gB = Bw + (size_t)colB0 * K;

    // prologue: stages 0..2
#pragma unroll
    for (int s = 0; s < NST - 1; s++) {
        gemm_load_stage(gA + (size_t)s * BK, gB + (size_t)s * BK,
                        sb + s * STAGE, sb + s * STAGE + A_BYTES, K, t);
        asm volatile("cp.async.commit_group;" ::: "memory");
    }

    // ldmatrix bases (unswizzled) + row masks; mask invariant under +kk*32
    // because lseg*16 + kk*32 <= 112 < 128 (no carry into bit 7).
    const int lrow = lane & 15;
    const int lseg = lane >> 4;
    uint32_t aOff[4], aM[4], bOff[4], bM[4];
#pragma unroll
    for (int i = 0; i < 4; i++) {
        uint32_t ao = (uint32_t)((wm * 64 + i * 16 + lrow) * 128 + lseg * 16);
        uint32_t bo = (uint32_t)((wn * 64 + i * 16 + lrow) * 128 + lseg * 16);
        aOff[i] = ao; aM[i] = (ao >> 3) & 0x70;
        bOff[i] = bo; bM[i] = (bo >> 3) & 0x70;
    }

    for (int kt = 0; kt < KT; kt++) {
        asm volatile("cp.async.wait_group %0;" :: "n"(NST - 2) : "memory");
        __syncthreads();

        const uint32_t sA = sb + (kt % NST) * STAGE;
        const uint32_t sB = sA + A_BYTES;

        // ---- kk = 0 first: get tensor pipe busy before the prefetch burst
        {
            uint32_t af[4][4], bf[8][2];
#pragma unroll
            for (int mi = 0; mi < 4; mi++)
                LDSM_X4(af[mi][0], af[mi][1], af[mi][2], af[mi][3],
                        sA + (aOff[mi] ^ aM[mi]));
#pragma unroll
            for (int nj = 0; nj < 4; nj++) {
                uint32_t r0, r1, r2, r3;
                LDSM_X4(r0, r1, r2, r3, sB + (bOff[nj] ^ bM[nj]));
                bf[2 * nj][0] = r0; bf[2 * nj][1] = r2;
                bf[2 * nj + 1][0] = r1; bf[2 * nj + 1][1] = r3;
            }
#pragma unroll
            for (int mi = 0; mi < 4; mi++)
#pragma unroll
                for (int ni = 0; ni < 8; ni++)
                    mma_f16(acc[mi][ni], af[mi], bf[ni]);
        }

        // ---- prefetch stage kt+3 while tensor pipe drains kk=0
        const int pf = kt + NST - 1;
        if (pf < KT)
            gemm_load_stage(gA + (size_t)pf * BK, gB + (size_t)pf * BK,
                            sb + (pf % NST) * STAGE, sb + (pf % NST) * STAGE + A_BYTES, K, t);
        asm volatile("cp.async.commit_group;" ::: "memory");

        // ---- kk = 1..3  (XOR applied AFTER the add)
#pragma unroll
        for (int kk = 1; kk < 4; kk++) {
            uint32_t af[4][4], bf[8][2];
#pragma unroll
            for (int mi = 0; mi < 4; mi++)
                LDSM_X4(af[mi][0], af[mi][1], af[mi][2], af[mi][3],
                        sA + ((aOff[mi] + kk * 32) ^ aM[mi]));
#pragma unroll
            for (int nj = 0; nj < 4; nj++) {
                uint32_t r0, r1, r2, r3;
                LDSM_X4(r0, r1, r2, r3, sB + ((bOff[nj] + kk * 32) ^ bM[nj]));
                bf[2 * nj][0] = r0; bf[2 * nj][1] = r2;
                bf[2 * nj + 1][0] = r1; bf[2 * nj + 1][1] = r3;
            }
#pragma unroll
            for (int mi = 0; mi < 4; mi++)
#pragma unroll
                for (int ni = 0; ni < 8; ni++)
                    mma_f16(acc[mi][ni], af[mi], bf[ni]);
        }
    }

    // epilogue
    const int gid = lane >> 2, tig = lane & 3;
#pragma unroll
    for (int mi = 0; mi < 4; mi++)
#pragma unroll
        for (int ni = 0; ni < 8; ni++) {
            const int row = rowA0 + wm * 64 + mi * 16 + gid;
            const int col = colB0 + wn * 64 + ni * 8 + 2 * tig;
            const float b0 = bias[col], b1 = bias[col + 1];
#pragma unroll
            for (int hh = 0; hh < 2; hh++) {
                const int r2 = row + hh * 8;
                float v0 = acc[mi][ni][hh * 2 + 0] + b0;
                float v1 = acc[mi][ni][hh * 2 + 1] + b1;
                if (MODE == 1 || MODE == 3) {
                    v0 += res[(size_t)r2 * N + col];
                    v1 += res[(size_t)r2 * N + col + 1];
                }
                if (MODE == 2) { v0 = gelu_exact(v0); v1 = gelu_exact(v1); }
                int ro = r2;
                if (MODE == 3) {
                    const int bb = r2 >> 12;
                    const int l  = r2 & (Lq - 1);
                    ro = (bb << 12) | ((l + SHIFTq) & (Lq - 1));
                }
                store2(C + (size_t)ro * N + col, v0, v1);
            }
        }
}

// ---------------------------------------------------------------------------
// Launch
// ---------------------------------------------------------------------------
template <typename T>
static T* sym_addr(const void* sym) { void* p; cudaGetSymbolAddress(&p, sym); return (T*)p; }

extern "C" void kernel_launch(void* const* d_in, const int* in_sizes, int n_in,
                              void* d_out, int out_size)
{
    (void)in_sizes; (void)n_in; (void)out_size;
    const float* x     = (const float*)d_in[0];
    const float* ln1_g = (const float*)d_in[1];
    const float* ln1_b = (const float*)d_in[2];
    const float* in_w  = (const float*)d_in[3];
    const float* in_b  = (const float*)d_in[4];
    const float* ow    = (const float*)d_in[5];
    const float* ob    = (const float*)d_in[6];
    const float* ln2_g = (const float*)d_in[7];
    const float* ln2_b = (const float*)d_in[8];
    const float* w1    = (const float*)d_in[9];
    const float* b1    = (const float*)d_in[10];
    const float* w2    = (const float*)d_in[11];
    const float* b2    = (const float*)d_in[12];
    float* out = (float*)d_out;

    float*  xs   = sym_addr<float>(g_xs);
    float*  xsum = sym_addr<float>(g_xsum);
    __half* qin  = sym_addr<__half>(g_qin);
    __half* qkv  = sym_addr<__half>(g_qkv);
    __half* attn = sym_addr<__half>(g_attn);
    __half* z    = sym_addr<__half>(g_z);
    __half* h1   = sym_addr<__half>(g_h1);
    __half* wqkv = sym_addr<__half>(g_wqkv);
    __half* wo   = sym_addr<__half>(g_wo);
    __half* w1h  = sym_addr<__half>(g_w1);
    __half* w2h  = sym_addr<__half>(g_w2);

    cudaFuncSetAttribute(gemm_f16<0, __half>, cudaFuncAttributeMaxDynamicSharedMemorySize, GSMEM);
    cudaFuncSetAttribute(gemm_f16<1, float>,  cudaFuncAttributeMaxDynamicSharedMemorySize, GSMEM);
    cudaFuncSetAttribute(gemm_f16<2, __half>, cudaFuncAttributeMaxDynamicSharedMemorySize, GSMEM);
    cudaFuncSetAttribute(gemm_f16<3, float>,  cudaFuncAttributeMaxDynamicSharedMemorySize, GSMEM);

    // 0. convert weights to fp16 (two launches)
    {
        int n0 = 3 * Hq * Hq, n1 = Hq * Hq;
        f2h2_kernel<<<((n0 + n1) / 4 + 255) / 256, 256>>>(in_w, wqkv, n0, ow, wo, n1);
        int n2 = FFq * Hq, n3 = Hq * FFq;
        f2h2_kernel<<<((n2 + n3) / 4 + 255) / 256, 256>>>(w1, w1h, n2, w2, w2h, n3);
    }

    // 1. roll(-SHIFT) + LN1 -> xs (f32), qin (f16)
    ln_kernel<<<Mq, 256>>>(x, ln1_g, ln1_b, xs, qin, SHIFTq);

    // 2. qkv = qin @ in_w^T + in_b          [16384, 3072] f16
    gemm_f16<0, __half><<<dim3(3 * Hq / BN, Mq / BM), 256, GSMEM>>>(
        qin, wqkv, in_b, nullptr, qkv, 3 * Hq, Hq);

    // 3. windowed attention -> attn (f16)
    attn_kernel<<<dim3(Bq * (Lq / Wq), NHq), 256>>>(qkv, attn);

    // 4. xsum = xs + attn @ ow^T + ob       [16384, 1024] f32
    gemm_f16<1, float><<<dim3(Hq / BN, Mq / BM), 256, GSMEM>>>(
        attn, wo, ob, xs, xsum, Hq, Hq);

    // 5. LN2 -> z (f16)
    ln_kernel<<<Mq, 256>>>(xsum, ln2_g, ln2_b, nullptr, z, 0);

    // 6. h1 = gelu(z @ w1^T + b1)           [16384, 4096] f16
    gemm_f16<2, __half><<<dim3(FFq / BN, Mq / BM), 256, GSMEM>>>(
        z, w1h, b1, nullptr, h1, FFq, Hq);

    // 7. out = roll(+SHIFT)(xsum + h1 @ w2^T + b2)   [16384, 1024] f32
    gemm_f16<3, float><<<dim3(Hq / BN, Mq / BM), 256, GSMEM>>>(
        h1, w2h, b2, xsum, out, Hq, FFq);
}

// round 7
// speedup vs baseline: 2.6284x; 1.0233x over previous
#include <cuda_runtime.h>
#include <cuda_fp16.h>
#include <cstdint>
#include <math.h>

// Problem constants
#define Bq     4
#define Lq     4096
#define Hq     1024
#define NHq    16
#define Wq     64
#define SHIFTq 32
#define FFq    4096
#define HDq    64
#define Mq     (Bq * Lq)   // 16384 rows

// ---------------------------------------------------------------------------
// Scratch (device globals)
// ---------------------------------------------------------------------------
__device__ float  g_xs  [(size_t)Mq * Hq];
__device__ float  g_xsum[(size_t)Mq * Hq];
__device__ __half g_qin [(size_t)Mq * Hq];
__device__ __half g_qkv [(size_t)Mq * 3 * Hq];
__device__ __half g_attn[(size_t)Mq * Hq];
__device__ __half g_z   [(size_t)Mq * Hq];
__device__ __half g_h1  [(size_t)Mq * FFq];
__device__ __half g_wqkv[(size_t)3 * Hq * Hq];
__device__ __half g_wo  [(size_t)Hq * Hq];
__device__ __half g_w1  [(size_t)FFq * Hq];
__device__ __half g_w2  [(size_t)Hq * FFq];

// ---------------------------------------------------------------------------
// Helpers
// ---------------------------------------------------------------------------
__device__ __forceinline__ uint32_t smem_u32(const void* p) {
    uint32_t a;
    asm("{ .reg .u64 t; cvta.to.shared.u64 t, %1; cvt.u32.u64 %0, t; }" : "=r"(a) : "l"(p));
    return a;
}

__device__ __forceinline__ void mma_f16(float c[4], const uint32_t a[4], const uint32_t b[2]) {
    asm volatile(
        "mma.sync.aligned.m16n8k16.row.col.f32.f16.f16.f32 "
        "{%0,%1,%2,%3}, {%4,%5,%6,%7}, {%8,%9}, {%0,%1,%2,%3};\n"
        : "+f"(c[0]), "+f"(c[1]), "+f"(c[2]), "+f"(c[3])
        : "r"(a[0]), "r"(a[1]), "r"(a[2]), "r"(a[3]), "r"(b[0]), "r"(b[1]));
}

#define LDSM_X4(r0, r1, r2, r3, addr) \
    asm volatile("ldmatrix.sync.aligned.m8n8.x4.shared.b16 {%0,%1,%2,%3}, [%4];" \
        : "=r"(r0), "=r"(r1), "=r"(r2), "=r"(r3) : "r"(addr))

#define CP_ASYNC16(dst, src) \
    asm volatile("cp.async.cg.shared.global [%0], [%1], 16;" :: "r"(dst), "l"(src))

__device__ __forceinline__ float gelu_exact(float v) {
    return 0.5f * v * (1.0f + erff(v * 0.70710678118654752f));
}

__device__ __forceinline__ void store2(float* p, float a, float b) {
    *reinterpret_cast<float2*>(p) = make_float2(a, b);
}
__device__ __forceinline__ void store2(__half* p, float a, float b) {
    *reinterpret_cast<__half2*>(p) = __floats2half2_rn(a, b);
}

// ---------------------------------------------------------------------------
// float -> half conversion, two arrays per launch
// ---------------------------------------------------------------------------
__global__ void __launch_bounds__(256)
f2h2_kernel(const float* __restrict__ s0, __half* __restrict__ d0, int n0,
            const float* __restrict__ s1, __half* __restrict__ d1, int n1)
{
    int i = (blockIdx.x * 256 + threadIdx.x) * 4;
    const float* s; __half* d;
    if (i < n0) { s = s0; d = d0; }
    else        { i -= n0; s = s1; d = d1; if (i >= n1) return; }
    float4 f = *reinterpret_cast<const float4*>(s + i);
    *reinterpret_cast<__half2*>(d + i)     = __floats2half2_rn(f.x, f.y);
    *reinterpret_cast<__half2*>(d + i + 2) = __floats2half2_rn(f.z, f.w);
}

// ---------------------------------------------------------------------------
// LayerNorm (+ roll read, + optional copy of rolled raw input); output half
// ---------------------------------------------------------------------------
__global__ void __launch_bounds__(256)
ln_kernel(const float* __restrict__ x, const float* __restrict__ g,
          const float* __restrict__ bb, float* __restrict__ xs_out,
          __half* __restrict__ y, int shift)
{
    const int row = blockIdx.x;
    const int b   = row >> 12;
    const int l   = row & (Lq - 1);
    const int sl  = (l + shift) & (Lq - 1);
    const float* px = x + ((size_t)(b * Lq + sl)) * Hq;

    const int t = threadIdx.x;
    float v[4];
    float s = 0.f, sq = 0.f;
#pragma unroll
    for (int i = 0; i < 4; i++) {
        v[i] = px[t + i * 256];
        s  += v[i];
        sq += v[i] * v[i];
    }
#pragma unroll
    for (int o = 16; o > 0; o >>= 1) {
        s  += __shfl_xor_sync(0xffffffffu, s,  o);
        sq += __shfl_xor_sync(0xffffffffu, sq, o);
    }
    __shared__ float ws[8], wq[8];
    const int lane = t & 31, warp = t >> 5;
    if (lane == 0) { ws[warp] = s; wq[warp] = sq; }
    __syncthreads();
    if (t == 0) {
        float S = 0.f, Q = 0.f;
#pragma unroll
        for (int w = 0; w < 8; w++) { S += ws[w]; Q += wq[w]; }
        float mu  = S * (1.0f / Hq);
        float var = Q * (1.0f / Hq) - mu * mu;
        ws[0] = mu;
        wq[0] = rsqrtf(var + 1e-5f);
    }
    __syncthreads();
    const float mu = ws[0], rstd = wq[0];

    __half* py = y + (size_t)row * Hq;
    float* pxs = xs_out ? xs_out + (size_t)row * Hq : nullptr;
#pragma unroll
    for (int i = 0; i < 4; i++) {
        int c = t + i * 256;
        float xv = v[i];
        py[c] = __float2half((xv - mu) * rstd * g[c] + bb[c]);
        if (pxs) pxs[c] = xv;
    }
}

// ---------------------------------------------------------------------------
// Windowed attention (fp16 in/out, fp32 compute)
// ---------------------------------------------------------------------------
__global__ void __launch_bounds__(256)
attn_kernel(const __half* __restrict__ qkv, __half* __restrict__ attn)
{
    const int bw = blockIdx.x;
    const int b  = bw >> 6;
    const int w  = bw & 63;
    const int h  = blockIdx.y;

    __shared__ float Qt[64 * 64];
    __shared__ float Ks[64 * 64];
    __shared__ float Vs[64 * 64];

    const int t = threadIdx.x;
    const int rowbase = b * Lq + w * 64;
    for (int idx = t; idx < 4096; idx += 256) {
        int i = idx >> 6, d = idx & 63;
        size_t base = (size_t)(rowbase + i) * (3 * Hq) + h * 64 + d;
        Qt[d * 64 + ((i + d) & 63)] = __half2float(qkv[base]);
        Ks[i * 64 + ((d + i) & 63)] = __half2float(qkv[base + Hq]);
        Vs[i * 64 + d]              = __half2float(qkv[base + 2 * Hq]);
    }
    __syncthreads();

    const int r = t >> 2, tig = t & 3;

    float s[16];
#pragma unroll
    for (int j = 0; j < 16; j++) s[j] = 0.f;
    for (int d = 0; d < 64; d++) {
        float qv = Qt[d * 64 + ((r + d) & 63)];
#pragma unroll
        for (int j = 0; j < 16; j++) {
            int c = tig + 4 * j;
            s[j] += qv * Ks[c * 64 + ((d + c) & 63)];
        }
    }
    float mx = -1e30f;
#pragma unroll
    for (int j = 0; j < 16; j++) { s[j] *= 0.125f; mx = fmaxf(mx, s[j]); }
    mx = fmaxf(mx, __shfl_xor_sync(0xffffffffu, mx, 1));
    mx = fmaxf(mx, __shfl_xor_sync(0xffffffffu, mx, 2));
    float sum = 0.f;
#pragma unroll
    for (int j = 0; j < 16; j++) { s[j] = expf(s[j] - mx); sum += s[j]; }
    sum += __shfl_xor_sync(0xffffffffu, sum, 1);
    sum += __shfl_xor_sync(0xffffffffu, sum, 2);
    const float inv = 1.0f / sum;
#pragma unroll
    for (int j = 0; j < 16; j++) s[j] *= inv;

    __syncthreads();
#pragma unroll
    for (int j = 0; j < 16; j++) Qt[(tig + 4 * j) * 64 + r] = s[j];
    __syncthreads();

    float acc[16];
#pragma unroll
    for (int j = 0; j < 16; j++) acc[j] = 0.f;
    for (int c = 0; c < 64; c++) {
        float pv = Qt[c * 64 + r];
#pragma unroll
        for (int j = 0; j < 16; j++)
            acc[j] += pv * Vs[c * 64 + tig + 4 * j];
    }
    __half* po = attn + (size_t)(rowbase + r) * Hq + h * 64;
#pragma unroll
    for (int j = 0; j < 16; j++) po[tig + 4 * j] = __float2half(acc[j]);
}

// ---------------------------------------------------------------------------
// fp16 GEMM, cp.async + ldmatrix:  C = A[M,K] @ W[N,K]^T + epi
// CTA 128x128x64, 8 warps (2x4), warp tile 64x32  -> 2 CTAs/SM (128 regs).
// 3-stage cp.async ring (96KB), SW128-swizzled rows.
// Mainloop: consume kk=0, then issue prefetch, then kk=1..3.
//   MODE 0: +bias   MODE 1: +bias+res   MODE 2: gelu(+bias)
//   MODE 3: +bias+res, stored with row roll(+SHIFT)
// ---------------------------------------------------------------------------
constexpr int BM = 128, BN = 128, BK = 64, NST = 3;
constexpr int A_BYTES = BM * BK * 2;   // 16384
constexpr int B_BYTES = BN * BK * 2;   // 16384
constexpr int STAGE   = A_BYTES + B_BYTES;   // 32768
constexpr int GSMEM   = NST * STAGE;         // 98304

__device__ __forceinline__ void gemm_load_stage(const __half* __restrict__ gA,
                                                const __half* __restrict__ gB,
                                                uint32_t sA, uint32_t sB, int K, int t)
{
#pragma unroll
    for (int i = 0; i < 4; i++) {
        int idx = t + i * 256;          // 0..1023 (128 rows x 8 chunks)
        int row = idx >> 3, seg = idx & 7;
        uint32_t off = (uint32_t)(row * 128 + seg * 16);
        uint32_t sw  = off ^ ((off >> 3) & 0x70);
        CP_ASYNC16(sA + sw, gA + (size_t)row * K + seg * 8);
    }
#pragma unroll
    for (int i = 0; i < 4; i++) {
        int idx = t + i * 256;
        int row = idx >> 3, seg = idx & 7;
        uint32_t off = (uint32_t)(row * 128 + seg * 16);
        uint32_t sw  = off ^ ((off >> 3) & 0x70);
        CP_ASYNC16(sB + sw, gB + (size_t)row * K + seg * 8);
    }
}

template <int MODE, typename OutT>
__global__ void __launch_bounds__(256, 2)
gemm_f16(const __half* __restrict__ A, const __half* __restrict__ Bw,
         const float* __restrict__ bias, const float* __restrict__ res,
         OutT* __restrict__ C, int N, int K)
{
    extern __shared__ char smem[];
    const uint32_t sb = smem_u32(smem);
    const int t    = threadIdx.x;
    const int lane = t & 31, warp = t >> 5;
    const int wm   = warp & 1, wn = warp >> 1;      // 2 x 4 warp grid
    const int rowA0 = blockIdx.y * BM;
    const int colB0 = blockIdx.x * BN;

    float acc[4][4][4];
#pragma unroll
    for (int mi = 0; mi < 4; mi++)
#pragma unroll
        for (int ni = 0; ni < 4; ni++)
#pragma unroll
            for (int c = 0; c < 4; c++) acc[mi][ni][c] = 0.f;

    const int KT = K / BK;
    const __half* gA = A  + (size_t)rowA0 * K;
    const __half* gB = Bw + (size_t)colB0 * K;

    // prologue: stages 0..1
#pragma unroll
    for (int s = 0; s < NST - 1; s++) {
        gemm_load_stage(gA + (size_t)s * BK, gB + (size_t)s * BK,
                        sb + s * STAGE, sb + s * STAGE + A_BYTES, K, t);
        asm volatile("cp.async.commit_group;" ::: "memory");
    }

    // ldmatrix bases (unswizzled) + row masks; mask invariant under +kk*32
    // (lseg*16 + kk*32 <= 112 < 128: no carry into bit 7).
    const int lrow = lane & 15;
    const int lseg = lane >> 4;
    uint32_t aOff[4], aM[4], bOff[2], bM[2];
#pragma unroll
    for (int i = 0; i < 4; i++) {
        uint32_t ao = (uint32_t)((wm * 64 + i * 16 + lrow) * 128 + lseg * 16);
        aOff[i] = ao; aM[i] = (ao >> 3) & 0x70;
    }
#pragma unroll
    for (int i = 0; i < 2; i++) {
        uint32_t bo = (uint32_t)((wn * 32 + i * 16 + lrow) * 128 + lseg * 16);
        bOff[i] = bo; bM[i] = (bo >> 3) & 0x70;
    }

    for (int kt = 0; kt < KT; kt++) {
        asm volatile("cp.async.wait_group %0;" :: "n"(NST - 2) : "memory");
        __syncthreads();

        const uint32_t sA = sb + (kt % NST) * STAGE;
        const uint32_t sB = sA + A_BYTES;

        // ---- kk = 0 first: tensor pipe busy before prefetch burst
        {
            uint32_t af[4][4], bf[4][2];
#pragma unroll
            for (int mi = 0; mi < 4; mi++)
                LDSM_X4(af[mi][0], af[mi][1], af[mi][2], af[mi][3],
                        sA + (aOff[mi] ^ aM[mi]));
#pragma unroll
            for (int nj = 0; nj < 2; nj++) {
                uint32_t r0, r1, r2, r3;
                LDSM_X4(r0, r1, r2, r3, sB + (bOff[nj] ^ bM[nj]));
                bf[2 * nj][0] = r0; bf[2 * nj][1] = r2;
                bf[2 * nj + 1][0] = r1; bf[2 * nj + 1][1] = r3;
            }
#pragma unroll
            for (int mi = 0; mi < 4; mi++)
#pragma unroll
                for (int ni = 0; ni < 4; ni++)
                    mma_f16(acc[mi][ni], af[mi], bf[ni]);
        }

        // ---- prefetch stage kt+2
        const int pf = kt + NST - 1;
        if (pf < KT)
            gemm_load_stage(gA + (size_t)pf * BK, gB + (size_t)pf * BK,
                            sb + (pf % NST) * STAGE, sb + (pf % NST) * STAGE + A_BYTES, K, t);
        asm volatile("cp.async.commit_group;" ::: "memory");

        // ---- kk = 1..3  (XOR applied AFTER the add)
#pragma unroll
        for (int kk = 1; kk < 4; kk++) {
            uint32_t af[4][4], bf[4][2];
#pragma unroll
            for (int mi = 0; mi < 4; mi++)
                LDSM_X4(af[mi][0], af[mi][1], af[mi][2], af[mi][3],
                        sA + ((aOff[mi] + kk * 32) ^ aM[mi]));
#pragma unroll
            for (int nj = 0; nj < 2; nj++) {
                uint32_t r0, r1, r2, r3;
                LDSM_X4(r0, r1, r2, r3, sB + ((bOff[nj] + kk * 32) ^ bM[nj]));
                bf[2 * nj][0] = r0; bf[2 * nj][1] = r2;
                bf[2 * nj + 1][0] = r1; bf[2 * nj + 1][1] = r3;
            }
#pragma unroll
            for (int mi = 0; mi < 4; mi++)
#pragma unroll
                for (int ni = 0; ni < 4; ni++)
                    mma_f16(acc[mi][ni], af[mi], bf[ni]);
        }
    }

    // epilogue
    const int gid = lane >> 2, tig = lane & 3;
#pragma unroll
    for (int mi = 0; mi < 4; mi++)
#pragma unroll
        for (int ni = 0; ni < 4; ni++) {
            const int row = rowA0 + wm * 64 + mi * 16 + gid;
            const int col = colB0 + wn * 32 + ni * 8 + 2 * tig;
            const float b0 = bias[col], b1 = bias[col + 1];
#pragma unroll
            for (int hh = 0; hh < 2; hh++) {
                const int r2 = row + hh * 8;
                float v0 = acc[mi][ni][hh * 2 + 0] + b0;
                float v1 = acc[mi][ni][hh * 2 + 1] + b1;
                if (MODE == 1 || MODE == 3) {
                    v0 += res[(size_t)r2 * N + col];
                    v1 += res[(size_t)r2 * N + col + 1];
                }
                if (MODE == 2) { v0 = gelu_exact(v0); v1 = gelu_exact(v1); }
                int ro = r2;
                if (MODE == 3) {
                    const int bb = r2 >> 12;
                    const int l  = r2 & (Lq - 1);
                    ro = (bb << 12) | ((l + SHIFTq) & (Lq - 1));
                }
                store2(C + (size_t)ro * N + col, v0, v1);
            }
        }
}

// ---------------------------------------------------------------------------
// Launch
// ---------------------------------------------------------------------------
template <typename T>
static T* sym_addr(const void* sym) { void* p; cudaGetSymbolAddress(&p, sym); return (T*)p; }

extern "C" void kernel_launch(void* const* d_in, const int* in_sizes, int n_in,
                              void* d_out, int out_size)
{
    (void)in_sizes; (void)n_in; (void)out_size;
    const float* x     = (const float*)d_in[0];
    const float* ln1_g = (const float*)d_in[1];
    const float* ln1_b = (const float*)d_in[2];
    const float* in_w  = (const float*)d_in[3];
    const float* in_b  = (const float*)d_in[4];
    const float* ow    = (const float*)d_in[5];
    const float* ob    = (const float*)d_in[6];
    const float* ln2_g = (const float*)d_in[7];
    const float* ln2_b = (const float*)d_in[8];
    const float* w1    = (const float*)d_in[9];
    const float* b1    = (const float*)d_in[10];
    const float* w2    = (const float*)d_in[11];
    const float* b2    = (const float*)d_in[12];
    float* out = (float*)d_out;

    float*  xs   = sym_addr<float>(g_xs);
    float*  xsum = sym_addr<float>(g_xsum);
    __half* qin  = sym_addr<__half>(g_qin);
    __half* qkv  = sym_addr<__half>(g_qkv);
    __half* attn = sym_addr<__half>(g_attn);
    __half* z    = sym_addr<__half>(g_z);
    __half* h1   = sym_addr<__half>(g_h1);
    __half* wqkv = sym_addr<__half>(g_wqkv);
    __half* wo   = sym_addr<__half>(g_wo);
    __half* w1h  = sym_addr<__half>(g_w1);
    __half* w2h  = sym_addr<__half>(g_w2);

    cudaFuncSetAttribute(gemm_f16<0, __half>, cudaFuncAttributeMaxDynamicSharedMemorySize, GSMEM);
    cudaFuncSetAttribute(gemm_f16<1, float>,  cudaFuncAttributeMaxDynamicSharedMemorySize, GSMEM);
    cudaFuncSetAttribute(gemm_f16<2, __half>, cudaFuncAttributeMaxDynamicSharedMemorySize, GSMEM);
    cudaFuncSetAttribute(gemm_f16<3, float>,  cudaFuncAttributeMaxDynamicSharedMemorySize, GSMEM);

    // 0. convert weights to fp16 (two launches)
    {
        int n0 = 3 * Hq * Hq, n1 = Hq * Hq;
        f2h2_kernel<<<((n0 + n1) / 4 + 255) / 256, 256>>>(in_w, wqkv, n0, ow, wo, n1);
        int n2 = FFq * Hq, n3 = Hq * FFq;
        f2h2_kernel<<<((n2 + n3) / 4 + 255) / 256, 256>>>(w1, w1h, n2, w2, w2h, n3);
    }

    // 1. roll(-SHIFT) + LN1 -> xs (f32), qin (f16)
    ln_kernel<<<Mq, 256>>>(x, ln1_g, ln1_b, xs, qin, SHIFTq);

    // 2. qkv = qin @ in_w^T + in_b          [16384, 3072] f16
    gemm_f16<0, __half><<<dim3(3 * Hq / BN, Mq / BM), 256, GSMEM>>>(
        qin, wqkv, in_b, nullptr, qkv, 3 * Hq, Hq);

    // 3. windowed attention -> attn (f16)
    attn_kernel<<<dim3(Bq * (Lq / Wq), NHq), 256>>>(qkv, attn);

    // 4. xsum = xs + attn @ ow^T + ob       [16384, 1024] f32
    gemm_f16<1, float><<<dim3(Hq / BN, Mq / BM), 256, GSMEM>>>(
        attn, wo, ob, xs, xsum, Hq, Hq);

    // 5. LN2 -> z (f16)
    ln_kernel<<<Mq, 256>>>(xsum, ln2_g, ln2_b, nullptr, z, 0);

    // 6. h1 = gelu(z @ w1^T + b1)           [16384, 4096] f16
    gemm_f16<2, __half><<<dim3(FFq / BN, Mq / BM), 256, GSMEM>>>(
        z, w1h, b1, nullptr, h1, FFq, Hq);

    // 7. out = roll(+SHIFT)(xsum + h1 @ w2^T + b2)   [16384, 1024] f32
    gemm_f16<3, float><<<dim3(Hq / BN, Mq / BM), 256, GSMEM>>>(
        h1, w2h, b2, xsum, out, Hq, FFq);
}

// round 8
// speedup vs baseline: 3.2385x; 1.2321x over previous
#include <cuda_runtime.h>
#include <cuda_fp16.h>
#include <cstdint>
#include <math.h>

// Problem constants
#define Bq     4
#define Lq     4096
#define Hq     1024
#define NHq    16
#define Wq     64
#define SHIFTq 32
#define FFq    4096
#define HDq    64
#define Mq     (Bq * Lq)   // 16384 rows

// ---------------------------------------------------------------------------
// Scratch (device globals)
// ---------------------------------------------------------------------------
__device__ float  g_xs  [(size_t)Mq * Hq];
__device__ float  g_xsum[(size_t)Mq * Hq];
__device__ __half g_qin [(size_t)Mq * Hq];
__device__ __half g_qkv [(size_t)Mq * 3 * Hq];
__device__ __half g_attn[(size_t)Mq * Hq];
__device__ __half g_z   [(size_t)Mq * Hq];
__device__ __half g_h1  [(size_t)Mq * FFq];
__device__ __half g_wqkv[(size_t)3 * Hq * Hq];
__device__ __half g_wo  [(size_t)Hq * Hq];
__device__ __half g_w1  [(size_t)FFq * Hq];
__device__ __half g_w2  [(size_t)Hq * FFq];

// ---------------------------------------------------------------------------
// Helpers
// ---------------------------------------------------------------------------
__device__ __forceinline__ uint32_t smem_u32(const void* p) {
    uint32_t a;
    asm("{ .reg .u64 t; cvta.to.shared.u64 t, %1; cvt.u32.u64 %0, t; }" : "=r"(a) : "l"(p));
    return a;
}

__device__ __forceinline__ void mma_f16(float c[4], const uint32_t a[4], const uint32_t b[2]) {
    asm volatile(
        "mma.sync.aligned.m16n8k16.row.col.f32.f16.f16.f32 "
        "{%0,%1,%2,%3}, {%4,%5,%6,%7}, {%8,%9}, {%0,%1,%2,%3};\n"
        : "+f"(c[0]), "+f"(c[1]), "+f"(c[2]), "+f"(c[3])
        : "r"(a[0]), "r"(a[1]), "r"(a[2]), "r"(a[3]), "r"(b[0]), "r"(b[1]));
}

#define LDSM_X4(r0, r1, r2, r3, addr) \
    asm volatile("ldmatrix.sync.aligned.m8n8.x4.shared.b16 {%0,%1,%2,%3}, [%4];" \
        : "=r"(r0), "=r"(r1), "=r"(r2), "=r"(r3) : "r"(addr))

#define CP_ASYNC16(dst, src) \
    asm volatile("cp.async.cg.shared.global [%0], [%1], 16;" :: "r"(dst), "l"(src))

__device__ __forceinline__ float gelu_exact(float v) {
    return 0.5f * v * (1.0f + erff(v * 0.70710678118654752f));
}

__device__ __forceinline__ void store2(float* p, float a, float b) {
    *reinterpret_cast<float2*>(p) = make_float2(a, b);
}
__device__ __forceinline__ void store2(__half* p, float a, float b) {
    *reinterpret_cast<__half2*>(p) = __floats2half2_rn(a, b);
}

__device__ __forceinline__ uint32_t packh2(float a, float b) {
    __half2 h = __floats2half2_rn(a, b);
    return *reinterpret_cast<uint32_t*>(&h);
}

// ---------------------------------------------------------------------------
// float -> half conversion, two arrays per launch
// ---------------------------------------------------------------------------
__global__ void __launch_bounds__(256)
f2h2_kernel(const float* __restrict__ s0, __half* __restrict__ d0, int n0,
            const float* __restrict__ s1, __half* __restrict__ d1, int n1)
{
    int i = (blockIdx.x * 256 + threadIdx.x) * 4;
    const float* s; __half* d;
    if (i < n0) { s = s0; d = d0; }
    else        { i -= n0; s = s1; d = d1; if (i >= n1) return; }
    float4 f = *reinterpret_cast<const float4*>(s + i);
    *reinterpret_cast<__half2*>(d + i)     = __floats2half2_rn(f.x, f.y);
    *reinterpret_cast<__half2*>(d + i + 2) = __floats2half2_rn(f.z, f.w);
}

// ---------------------------------------------------------------------------
// LayerNorm (+ roll read, + optional copy of rolled raw input); output half
// ---------------------------------------------------------------------------
__global__ void __launch_bounds__(256)
ln_kernel(const float* __restrict__ x, const float* __restrict__ g,
          const float* __restrict__ bb, float* __restrict__ xs_out,
          __half* __restrict__ y, int shift)
{
    const int row = blockIdx.x;
    const int b   = row >> 12;
    const int l   = row & (Lq - 1);
    const int sl  = (l + shift) & (Lq - 1);
    const float* px = x + ((size_t)(b * Lq + sl)) * Hq;

    const int t = threadIdx.x;
    float v[4];
    float s = 0.f, sq = 0.f;
#pragma unroll
    for (int i = 0; i < 4; i++) {
        v[i] = px[t + i * 256];
        s  += v[i];
        sq += v[i] * v[i];
    }
#pragma unroll
    for (int o = 16; o > 0; o >>= 1) {
        s  += __shfl_xor_sync(0xffffffffu, s,  o);
        sq += __shfl_xor_sync(0xffffffffu, sq, o);
    }
    __shared__ float ws[8], wq[8];
    const int lane = t & 31, warp = t >> 5;
    if (lane == 0) { ws[warp] = s; wq[warp] = sq; }
    __syncthreads();
    if (t == 0) {
        float S = 0.f, Q = 0.f;
#pragma unroll
        for (int w = 0; w < 8; w++) { S += ws[w]; Q += wq[w]; }
        float mu  = S * (1.0f / Hq);
        float var = Q * (1.0f / Hq) - mu * mu;
        ws[0] = mu;
        wq[0] = rsqrtf(var + 1e-5f);
    }
    __syncthreads();
    const float mu = ws[0], rstd = wq[0];

    __half* py = y + (size_t)row * Hq;
    float* pxs = xs_out ? xs_out + (size_t)row * Hq : nullptr;
#pragma unroll
    for (int i = 0; i < 4; i++) {
        int c = t + i * 256;
        float xv = v[i];
        py[c] = __float2half((xv - mu) * rstd * g[c] + bb[c]);
        if (pxs) pxs[c] = xv;
    }
}

// ---------------------------------------------------------------------------
// Tensor-core windowed attention.
// Block = 128 threads (4 warps) = one window x 2 heads; warp = 32 q-rows of
// one head. Q/K cp.async -> SW128 smem; V transposed into smem (so P@V uses
// the same verified non-trans ldmatrix B path); S in registers; softmax via
// quad shuffles; P repacked from S accumulator layout into A fragments.
// ---------------------------------------------------------------------------
constexpr int ATT_HEAD_BYTES = 24576;            // Q 8K + K 8K + Vt 8K
constexpr int ATT_SMEM = 2 * ATT_HEAD_BYTES;     // 49152

__global__ void __launch_bounds__(128)
attn_mma_kernel(const __half* __restrict__ qkv, __half* __restrict__ attn)
{
    extern __shared__ char asmem[];
    const uint32_t sb = smem_u32(asmem);
    const int bw = blockIdx.x;                   // b*64 + w
    const int b  = bw >> 6, w = bw & 63;
    const int h0 = blockIdx.y * 2;
    const int rowbase = b * Lq + w * 64;
    const int t = threadIdx.x;

    // ---- load Q, K via cp.async (SW128 swizzle, 128B rows per head)
#pragma unroll
    for (int hh = 0; hh < 2; hh++) {
        const uint32_t qs = sb + hh * ATT_HEAD_BYTES;
        const uint32_t ks = qs + 8192;
#pragma unroll
        for (int i = 0; i < 4; i++) {
            int idx = t + i * 128;               // 0..511
            int row = idx >> 3, ch = idx & 7;
            uint32_t off = (uint32_t)(row * 128 + ch * 16);
            uint32_t sw = off ^ ((off >> 3) & 0x70);
            const __half* gq = qkv + (size_t)(rowbase + row) * 3072 + (h0 + hh) * 64 + ch * 8;
            CP_ASYNC16(qs + sw, gq);
            CP_ASYNC16(ks + sw, gq + 1024);
        }
    }
    asm volatile("cp.async.commit_group;" ::: "memory");

    // ---- V: global load + transposed store to smem Vt[d][c] (128B rows)
#pragma unroll
    for (int hh = 0; hh < 2; hh++) {
        char* vtp = asmem + hh * ATT_HEAD_BYTES + 16384;
#pragma unroll
        for (int i = 0; i < 4; i++) {
            int idx = t + i * 128;
            int c = idx >> 3, ch = idx & 7;
            const __half* gv = qkv + (size_t)(rowbase + c) * 3072 + 2048 + (h0 + hh) * 64 + ch * 8;
            uint4 v = *reinterpret_cast<const uint4*>(gv);
            const __half* hv = reinterpret_cast<const __half*>(&v);
#pragma unroll
            for (int j = 0; j < 8; j++) {
                int d = ch * 8 + j;
                uint32_t off = (uint32_t)(d * 128 + c * 2);
                uint32_t sw = off ^ ((off >> 3) & 0x70);
                *reinterpret_cast<__half*>(vtp + sw) = hv[j];
            }
        }
    }
    asm volatile("cp.async.wait_group 0;" ::: "memory");
    __syncthreads();

    // ---- per-warp compute
    const int warp = t >> 5, lane = t & 31;
    const int hh = warp >> 1, mh = warp & 1;
    const uint32_t qs = sb + hh * ATT_HEAD_BYTES;
    const uint32_t ks = qs + 8192;
    const uint32_t vt = qs + 16384;
    const int lrow = lane & 15, lseg = lane >> 4;
    const int gid = lane >> 2, tig = lane & 3;

    // ldmatrix addresses (add-then-XOR; mask from row bits only)
    uint32_t qOff[2], qM[2], nOff[4], nM[4];
#pragma unroll
    for (int mt = 0; mt < 2; mt++) {
        int row = mh * 32 + mt * 16 + lrow;
        qOff[mt] = (uint32_t)(row * 128 + lseg * 16);
        qM[mt]   = (uint32_t)((row & 7) << 4);
    }
#pragma unroll
    for (int g = 0; g < 4; g++) {
        int row = g * 16 + lrow;
        nOff[g] = (uint32_t)(row * 128 + lseg * 16);
        nM[g]   = (uint32_t)((row & 7) << 4);
    }

    // S = Q @ K^T
    float S[2][8][4];
#pragma unroll
    for (int mt = 0; mt < 2; mt++)
#pragma unroll
        for (int nj = 0; nj < 8; nj++)
#pragma unroll
            for (int c = 0; c < 4; c++) S[mt][nj][c] = 0.f;

#pragma unroll
    for (int kt = 0; kt < 4; kt++) {
        uint32_t af[2][4], bf[8][2];
#pragma unroll
        for (int mt = 0; mt < 2; mt++)
            LDSM_X4(af[mt][0], af[mt][1], af[mt][2], af[mt][3],
                    qs + ((qOff[mt] + kt * 32) ^ qM[mt]));
#pragma unroll
        for (int g = 0; g < 4; g++) {
            uint32_t r0, r1, r2, r3;
            LDSM_X4(r0, r1, r2, r3, ks + ((nOff[g] + kt * 32) ^ nM[g]));
            bf[2 * g][0] = r0; bf[2 * g][1] = r2;
            bf[2 * g + 1][0] = r1; bf[2 * g + 1][1] = r3;
        }
#pragma unroll
        for (int mt = 0; mt < 2; mt++)
#pragma unroll
            for (int nj = 0; nj < 8; nj++)
                mma_f16(S[mt][nj], af[mt], bf[nj]);
    }

    // softmax (rows gid / gid+8 per m-tile), scale = 1/8
    float mx[2][2], sum[2][2];
#pragma unroll
    for (int mt = 0; mt < 2; mt++) { mx[mt][0] = -1e30f; mx[mt][1] = -1e30f; }
#pragma unroll
    for (int mt = 0; mt < 2; mt++)
#pragma unroll
        for (int nj = 0; nj < 8; nj++) {
#pragma unroll
            for (int c = 0; c < 4; c++) S[mt][nj][c] *= 0.125f;
            mx[mt][0] = fmaxf(mx[mt][0], fmaxf(S[mt][nj][0], S[mt][nj][1]));
            mx[mt][1] = fmaxf(mx[mt][1], fmaxf(S[mt][nj][2], S[mt][nj][3]));
        }
#pragma unroll
    for (int mt = 0; mt < 2; mt++)
#pragma unroll
        for (int rr = 0; rr < 2; rr++) {
            mx[mt][rr] = fmaxf(mx[mt][rr], __shfl_xor_sync(0xffffffffu, mx[mt][rr], 1));
            mx[mt][rr] = fmaxf(mx[mt][rr], __shfl_xor_sync(0xffffffffu, mx[mt][rr], 2));
        }
#pragma unroll
    for (int mt = 0; mt < 2; mt++) { sum[mt][0] = 0.f; sum[mt][1] = 0.f; }
#pragma unroll
    for (int mt = 0; mt < 2; mt++)
#pragma unroll
        for (int nj = 0; nj < 8; nj++) {
            S[mt][nj][0] = expf(S[mt][nj][0] - mx[mt][0]);
            S[mt][nj][1] = expf(S[mt][nj][1] - mx[mt][0]);
            S[mt][nj][2] = expf(S[mt][nj][2] - mx[mt][1]);
            S[mt][nj][3] = expf(S[mt][nj][3] - mx[mt][1]);
            sum[mt][0] += S[mt][nj][0] + S[mt][nj][1];
            sum[mt][1] += S[mt][nj][2] + S[mt][nj][3];
        }
#pragma unroll
    for (int mt = 0; mt < 2; mt++)
#pragma unroll
        for (int rr = 0; rr < 2; rr++) {
            sum[mt][rr] += __shfl_xor_sync(0xffffffffu, sum[mt][rr], 1);
            sum[mt][rr] += __shfl_xor_sync(0xffffffffu, sum[mt][rr], 2);
        }

    // O = P @ V  (P = unnormalized exp, packed from S regs; normalize at store)
    float O[2][8][4];
#pragma unroll
    for (int mt = 0; mt < 2; mt++)
#pragma unroll
        for (int nj = 0; nj < 8; nj++)
#pragma unroll
            for (int c = 0; c < 4; c++) O[mt][nj][c] = 0.f;

#pragma unroll
    for (int kt = 0; kt < 4; kt++) {
        uint32_t bf[8][2];
#pragma unroll
        for (int g = 0; g < 4; g++) {
            uint32_t r0, r1, r2, r3;
            LDSM_X4(r0, r1, r2, r3, vt + ((nOff[g] + kt * 32) ^ nM[g]));
            bf[2 * g][0] = r0; bf[2 * g][1] = r2;
            bf[2 * g + 1][0] = r1; bf[2 * g + 1][1] = r3;
        }
#pragma unroll
        for (int mt = 0; mt < 2; mt++) {
            uint32_t af[4];
            af[0] = packh2(S[mt][2 * kt][0],     S[mt][2 * kt][1]);
            af[1] = packh2(S[mt][2 * kt][2],     S[mt][2 * kt][3]);
            af[2] = packh2(S[mt][2 * kt + 1][0], S[mt][2 * kt + 1][1]);
            af[3] = packh2(S[mt][2 * kt + 1][2], S[mt][2 * kt + 1][3]);
#pragma unroll
            for (int nj = 0; nj < 8; nj++)
                mma_f16(O[mt][nj], af, bf[nj]);
        }
    }

    // store (normalize rows by 1/sum)
#pragma unroll
    for (int mt = 0; mt < 2; mt++) {
        const float inv0 = 1.0f / sum[mt][0];
        const float inv1 = 1.0f / sum[mt][1];
        const int row0 = rowbase + mh * 32 + mt * 16 + gid;
#pragma unroll
        for (int nj = 0; nj < 8; nj++) {
            const int col = (h0 + hh) * 64 + nj * 8 + 2 * tig;
            store2(attn + (size_t)row0 * Hq + col,       O[mt][nj][0] * inv0, O[mt][nj][1] * inv0);
            store2(attn + (size_t)(row0 + 8) * Hq + col, O[mt][nj][2] * inv1, O[mt][nj][3] * inv1);
        }
    }
}

// ---------------------------------------------------------------------------
// fp16 GEMM (unchanged from R7): CTA 128x128x64, warp tile 64x32, 2 CTAs/SM.
// ---------------------------------------------------------------------------
constexpr int BM = 128, BN = 128, BK = 64, NST = 3;
constexpr int A_BYTES = BM * BK * 2;
constexpr int B_BYTES = BN * BK * 2;
constexpr int STAGE   = A_BYTES + B_BYTES;
constexpr int GSMEM   = NST * STAGE;

__device__ __forceinline__ void gemm_load_stage(const __half* __restrict__ gA,
                                                const __half* __restrict__ gB,
                                                uint32_t sA, uint32_t sB, int K, int t)
{
#pragma unroll
    for (int i = 0; i < 4; i++) {
        int idx = t + i * 256;
        int row = idx >> 3, seg = idx & 7;
        uint32_t off = (uint32_t)(row * 128 + seg * 16);
        uint32_t sw  = off ^ ((off >> 3) & 0x70);
        CP_ASYNC16(sA + sw, gA + (size_t)row * K + seg * 8);
    }
#pragma unroll
    for (int i = 0; i < 4; i++) {
        int idx = t + i * 256;
        int row = idx >> 3, seg = idx & 7;
        uint32_t off = (uint32_t)(row * 128 + seg * 16);
        uint32_t sw  = off ^ ((off >> 3) & 0x70);
        CP_ASYNC16(sB + sw, gB + (size_t)row * K + seg * 8);
    }
}

template <int MODE, typename OutT>
__global__ void __launch_bounds__(256, 2)
gemm_f16(const __half* __restrict__ A, const __half* __restrict__ Bw,
         const float* __restrict__ bias, const float* __restrict__ res,
         OutT* __restrict__ C, int N, int K)
{
    extern __shared__ char smem[];
    const uint32_t sb = smem_u32(smem);
    const int t    = threadIdx.x;
    const int lane = t & 31, warp = t >> 5;
    const int wm   = warp & 1, wn = warp >> 1;
    const int rowA0 = blockIdx.y * BM;
    const int colB0 = blockIdx.x * BN;

    float acc[4][4][4];
#pragma unroll
    for (int mi = 0; mi < 4; mi++)
#pragma unroll
        for (int ni = 0; ni < 4; ni++)
#pragma unroll
            for (int c = 0; c < 4; c++) acc[mi][ni][c] = 0.f;

    const int KT = K / BK;
    const __half* gA = A  + (size_t)rowA0 * K;
    const __half* gB = Bw + (size_t)colB0 * K;

#pragma unroll
    for (int s = 0; s < NST - 1; s++) {
        gemm_load_stage(gA + (size_t)s * BK, gB + (size_t)s * BK,
                        sb + s * STAGE, sb + s * STAGE + A_BYTES, K, t);
        asm volatile("cp.async.commit_group;" ::: "memory");
    }

    const int lrow = lane & 15;
    const int lseg = lane >> 4;
    uint32_t aOff[4], aM[4], bOff[2], bM[2];
#pragma unroll
    for (int i = 0; i < 4; i++) {
        uint32_t ao = (uint32_t)((wm * 64 + i * 16 + lrow) * 128 + lseg * 16);
        aOff[i] = ao; aM[i] = (ao >> 3) & 0x70;
    }
#pragma unroll
    for (int i = 0; i < 2; i++) {
        uint32_t bo = (uint32_t)((wn * 32 + i * 16 + lrow) * 128 + lseg * 16);
        bOff[i] = bo; bM[i] = (bo >> 3) & 0x70;
    }

    for (int kt = 0; kt < KT; kt++) {
        asm volatile("cp.async.wait_group %0;" :: "n"(NST - 2) : "memory");
        __syncthreads();

        const uint32_t sA = sb + (kt % NST) * STAGE;
        const uint32_t sB = sA + A_BYTES;

        {
            uint32_t af[4][4], bf[4][2];
#pragma unroll
            for (int mi = 0; mi < 4; mi++)
                LDSM_X4(af[mi][0], af[mi][1], af[mi][2], af[mi][3],
                        sA + (aOff[mi] ^ aM[mi]));
#pragma unroll
            for (int nj = 0; nj < 2; nj++) {
                uint32_t r0, r1, r2, r3;
                LDSM_X4(r0, r1, r2, r3, sB + (bOff[nj] ^ bM[nj]));
                bf[2 * nj][0] = r0; bf[2 * nj][1] = r2;
                bf[2 * nj + 1][0] = r1; bf[2 * nj + 1][1] = r3;
            }
#pragma unroll
            for (int mi = 0; mi < 4; mi++)
#pragma unroll
                for (int ni = 0; ni < 4; ni++)
                    mma_f16(acc[mi][ni], af[mi], bf[ni]);
        }

        const int pf = kt + NST - 1;
        if (pf < KT)
            gemm_load_stage(gA + (size_t)pf * BK, gB + (size_t)pf * BK,
                            sb + (pf % NST) * STAGE, sb + (pf % NST) * STAGE + A_BYTES, K, t);
        asm volatile("cp.async.commit_group;" ::: "memory");

#pragma unroll
        for (int kk = 1; kk < 4; kk++) {
            uint32_t af[4][4], bf[4][2];
#pragma unroll
            for (int mi = 0; mi < 4; mi++)
                LDSM_X4(af[mi][0], af[mi][1], af[mi][2], af[mi][3],
                        sA + ((aOff[mi] + kk * 32) ^ aM[mi]));
#pragma unroll
            for (int nj = 0; nj < 2; nj++) {
                uint32_t r0, r1, r2, r3;
                LDSM_X4(r0, r1, r2, r3, sB + ((bOff[nj] + kk * 32) ^ bM[nj]));
                bf[2 * nj][0] = r0; bf[2 * nj][1] = r2;
                bf[2 * nj + 1][0] = r1; bf[2 * nj + 1][1] = r3;
            }
#pragma unroll
            for (int mi = 0; mi < 4; mi++)
#pragma unroll
                for (int ni = 0; ni < 4; ni++)
                    mma_f16(acc[mi][ni], af[mi], bf[ni]);
        }
    }

    const int gid = lane >> 2, tig = lane & 3;
#pragma unroll
    for (int mi = 0; mi < 4; mi++)
#pragma unroll
        for (int ni = 0; ni < 4; ni++) {
            const int row = rowA0 + wm * 64 + mi * 16 + gid;
            const int col = colB0 + wn * 32 + ni * 8 + 2 * tig;
            const float b0 = bias[col], b1 = bias[col + 1];
#pragma unroll
            for (int hh = 0; hh < 2; hh++) {
                const int r2 = row + hh * 8;
                float v0 = acc[mi][ni][hh * 2 + 0] + b0;
                float v1 = acc[mi][ni][hh * 2 + 1] + b1;
                if (MODE == 1 || MODE == 3) {
                    v0 += res[(size_t)r2 * N + col];
                    v1 += res[(size_t)r2 * N + col + 1];
                }
                if (MODE == 2) { v0 = gelu_exact(v0); v1 = gelu_exact(v1); }
                int ro = r2;
                if (MODE == 3) {
                    const int bb = r2 >> 12;
                    const int l  = r2 & (Lq - 1);
                    ro = (bb << 12) | ((l + SHIFTq) & (Lq - 1));
                }
                store2(C + (size_t)ro * N + col, v0, v1);
            }
        }
}

// ---------------------------------------------------------------------------
// Launch
// ---------------------------------------------------------------------------
template <typename T>
static T* sym_addr(const void* sym) { void* p; cudaGetSymbolAddress(&p, sym); return (T*)p; }

extern "C" void kernel_launch(void* const* d_in, const int* in_sizes, int n_in,
                              void* d_out, int out_size)
{
    (void)in_sizes; (void)n_in; (void)out_size;
    const float* x     = (const float*)d_in[0];
    const float* ln1_g = (const float*)d_in[1];
    const float* ln1_b = (const float*)d_in[2];
    const float* in_w  = (const float*)d_in[3];
    const float* in_b  = (const float*)d_in[4];
    const float* ow    = (const float*)d_in[5];
    const float* ob    = (const float*)d_in[6];
    const float* ln2_g = (const float*)d_in[7];
    const float* ln2_b = (const float*)d_in[8];
    const float* w1    = (const float*)d_in[9];
    const float* b1    = (const float*)d_in[10];
    const float* w2    = (const float*)d_in[11];
    const float* b2    = (const float*)d_in[12];
    float* out = (float*)d_out;

    float*  xs   = sym_addr<float>(g_xs);
    float*  xsum = sym_addr<float>(g_xsum);
    __half* qin  = sym_addr<__half>(g_qin);
    __half* qkv  = sym_addr<__half>(g_qkv);
    __half* attn = sym_addr<__half>(g_attn);
    __half* z    = sym_addr<__half>(g_z);
    __half* h1   = sym_addr<__half>(g_h1);
    __half* wqkv = sym_addr<__half>(g_wqkv);
    __half* wo   = sym_addr<__half>(g_wo);
    __half* w1h  = sym_addr<__half>(g_w1);
    __half* w2h  = sym_addr<__half>(g_w2);

    cudaFuncSetAttribute(gemm_f16<0, __half>, cudaFuncAttributeMaxDynamicSharedMemorySize, GSMEM);
    cudaFuncSetAttribute(gemm_f16<1, float>,  cudaFuncAttributeMaxDynamicSharedMemorySize, GSMEM);
    cudaFuncSetAttribute(gemm_f16<2, __half>, cudaFuncAttributeMaxDynamicSharedMemorySize, GSMEM);
    cudaFuncSetAttribute(gemm_f16<3, float>,  cudaFuncAttributeMaxDynamicSharedMemorySize, GSMEM);
    cudaFuncSetAttribute(attn_mma_kernel,     cudaFuncAttributeMaxDynamicSharedMemorySize, ATT_SMEM);

    // 0. convert weights to fp16 (two launches)
    {
        int n0 = 3 * Hq * Hq, n1 = Hq * Hq;
        f2h2_kernel<<<((n0 + n1) / 4 + 255) / 256, 256>>>(in_w, wqkv, n0, ow, wo, n1);
        int n2 = FFq * Hq, n3 = Hq * FFq;
        f2h2_kernel<<<((n2 + n3) / 4 + 255) / 256, 256>>>(w1, w1h, n2, w2, w2h, n3);
    }

    // 1. roll(-SHIFT) + LN1 -> xs (f32), qin (f16)
    ln_kernel<<<Mq, 256>>>(x, ln1_g, ln1_b, xs, qin, SHIFTq);

    // 2. qkv = qin @ in_w^T + in_b          [16384, 3072] f16
    gemm_f16<0, __half><<<dim3(3 * Hq / BN, Mq / BM), 256, GSMEM>>>(
        qin, wqkv, in_b, nullptr, qkv, 3 * Hq, Hq);

    // 3. windowed attention (tensor-core) -> attn (f16)
    attn_mma_kernel<<<dim3(Bq * (Lq / Wq), NHq / 2), 128, ATT_SMEM>>>(qkv, attn);

    // 4. xsum = xs + attn @ ow^T + ob       [16384, 1024] f32
    gemm_f16<1, float><<<dim3(Hq / BN, Mq / BM), 256, GSMEM>>>(
        attn, wo, ob, xs, xsum, Hq, Hq);

    // 5. LN2 -> z (f16)
    ln_kernel<<<Mq, 256>>>(xsum, ln2_g, ln2_b, nullptr, z, 0);

    // 6. h1 = gelu(z @ w1^T + b1)           [16384, 4096] f16
    gemm_f16<2, __half><<<dim3(FFq / BN, Mq / BM), 256, GSMEM>>>(
        z, w1h, b1, nullptr, h1, FFq, Hq);

    // 7. out = roll(+SHIFT)(xsum + h1 @ w2^T + b2)   [16384, 1024] f32
    gemm_f16<3, float><<<dim3(Hq / BN, Mq / BM), 256, GSMEM>>>(
        h1, w2h, b2, xsum, out, Hq, FFq);
}